// round 7
// baseline (speedup 1.0000x reference)
#include <cuda_runtime.h>
#include <cuda_bf16.h>
#include <math.h>
#include <stdint.h>

// ---------------- problem constants ----------------
#define BB   8
#define CC   256
#define LL   512
#define NG   32      // groups
#define CPG  8       // channels per group
#define NH   8       // heads
#define DH   32      // head dim
#define EE   1024    // experts
#define HIDD 32
#define CAPP 4
#define NTOK 256     // tokens per batch for MoE (=C)
#define DTOK 512     // token dim for MoE (=L)

// ---------------- scratch (device globals; allocation-free) ----------------
__device__ float g_x1[BB*CC*LL];
__device__ float g_h [BB*CC*LL];
__device__ float g_r [BB*CC*LL];
__device__ float g_xa[BB*CC*LL];
__device__ float g_t [BB*LL*3*CC];
__device__ float g_q [BB*NH*LL*DH];
__device__ float g_k [BB*NH*LL*DH];
__device__ float g_v [BB*NH*LL*DH];
__device__ float g_s [(size_t)BB*NH*LL*LL];
__device__ float g_oc[BB*LL*CC];
__device__ float g_xb[BB*CC*LL];
__device__ float g_xm[BB*CC*LL];
__device__ float g_logits[BB*NTOK*EE];
__device__ float g_raw  [BB*NTOK*EE];
__device__ float g_gate1[BB*NTOK];
__device__ float g_gate2[BB*NTOK];
__device__ int   g_i1[BB*NTOK];
__device__ int   g_i2[BB*NTOK];
__device__ float g_rawsum[BB*EE];
__device__ float g_cnt1 [BB*EE];
__device__ int   g_slot_tok [BB*EE*CAPP];
__device__ float g_slot_gate[BB*EE*CAPP];
__device__ float g_moeout[BB*CC*LL];
__device__ float g_yfull[(size_t)BB*2*CC*LL];

__device__ __forceinline__ float gelu_exact(float v) {
    return 0.5f * v * (1.0f + erff(v * 0.7071067811865476f));
}

// ================= warp-level bf16 MMA (m16n8k16, f32 accum) =================
__device__ __forceinline__ void mma16816(float* c, const uint32_t* a, const uint32_t* b) {
    asm volatile("mma.sync.aligned.m16n8k16.row.col.f32.bf16.bf16.f32 "
        "{%0,%1,%2,%3}, {%4,%5,%6,%7}, {%8,%9}, {%0,%1,%2,%3};"
        : "+f"(c[0]), "+f"(c[1]), "+f"(c[2]), "+f"(c[3])
        : "r"(a[0]), "r"(a[1]), "r"(a[2]), "r"(a[3]), "r"(b[0]), "r"(b[1]));
}

// ================= tensor-core conv1d(k=3,pad=1): C[m][n]=sum_k W[m][k]*X[k][n] =================
// fp32 emulated via bf16 hi/lo split (hi*hi + hi*lo + lo*hi).
// CTA: 128m x 128n, 256 threads = 8 warps (2m x 4n), warp tile 64m x 32n.
// K = 768 in 12 chunks of 64.
#define CPITCH 72           // smem row pitch in bf16 elems (conflict-free: bank=(4g+tg)%32)
#define OFF_AHI 0
#define OFF_ALO (128*CPITCH)
#define OFF_BHI (2*128*CPITCH)
#define OFF_BLO (3*128*CPITCH)
#define CONV_SMEM (4*128*CPITCH*2)   // 73728 bytes

__global__ void __launch_bounds__(256, 1)
conv_mma_kernel(const float* __restrict__ W, const float* __restrict__ X,
                const float* __restrict__ bias, const float* __restrict__ res,
                float* __restrict__ Y, int M) {
    extern __shared__ __nv_bfloat16 sm[];
    int tid = threadIdx.x;
    int wid = tid >> 5, lane = tid & 31;
    int g = lane >> 2, tg = lane & 3;
    int warp_m = wid & 1, warp_n = wid >> 1;      // 2 x 4
    int n0 = blockIdx.x * 128, m0 = blockIdx.y * 128;
    int bI = n0 >> 9, l0 = n0 & 511;

    const float* Wb = W + (size_t)m0 * 768;
    const float* Xb = X + (((size_t)bI * CC) << 9);

    float acc[4][4][4];
#pragma unroll
    for (int mi = 0; mi < 4; mi++)
#pragma unroll
        for (int ni = 0; ni < 4; ni++)
#pragma unroll
            for (int r = 0; r < 4; r++) acc[mi][ni][r] = 0.f;

    // B fill indices: each thread owns one (n, k-half)
    int fb_n = tid >> 1, fb_h = (tid & 1) * 32;

    for (int c = 0; c < 12; c++) {
        int c64 = c * 64;
        // ---- fill A: 128m x 64k (hi/lo) ----
#pragma unroll 8
        for (int i = 0; i < 32; i++) {
            int idx = i * 256 + tid;
            int m = idx >> 6, k = idx & 63;
            float w = Wb[(size_t)m * 768 + c64 + k];
            __nv_bfloat16 hi = __float2bfloat16(w);
            __nv_bfloat16 lo = __float2bfloat16(w - __bfloat162float(hi));
            sm[OFF_AHI + m * CPITCH + k] = hi;
            sm[OFF_ALO + m * CPITCH + k] = lo;
        }
        // ---- fill B: 128n x 64k (hi/lo), conv gather with halo ----
        {
            int l = l0 + fb_n;
#pragma unroll 8
            for (int i = 0; i < 32; i++) {
                int kg = c64 + fb_h + i;
                int ic = kg / 3, t = kg - 3 * ic;
                int ll = l + t - 1;
                float v = ((unsigned)ll < 512u) ? Xb[((size_t)ic << 9) + ll] : 0.f;
                __nv_bfloat16 hi = __float2bfloat16(v);
                __nv_bfloat16 lo = __float2bfloat16(v - __bfloat162float(hi));
                sm[OFF_BHI + fb_n * CPITCH + fb_h + i] = hi;
                sm[OFF_BLO + fb_n * CPITCH + fb_h + i] = lo;
            }
        }
        __syncthreads();
#pragma unroll
        for (int ks = 0; ks < 4; ks++) {
            int k0 = ks * 16;
            uint32_t ahi[4][4], alo[4][4], bhi[4][2], blo[4][2];
#pragma unroll
            for (int mi = 0; mi < 4; mi++) {
                int r0 = warp_m * 64 + mi * 16 + g;
                const __nv_bfloat16* p0 = &sm[OFF_AHI + r0 * CPITCH + k0 + tg * 2];
                const __nv_bfloat16* p1 = p0 + 8 * CPITCH;
                ahi[mi][0] = *(const uint32_t*)p0;
                ahi[mi][1] = *(const uint32_t*)p1;
                ahi[mi][2] = *(const uint32_t*)(p0 + 8);
                ahi[mi][3] = *(const uint32_t*)(p1 + 8);
                const __nv_bfloat16* q0 = &sm[OFF_ALO + r0 * CPITCH + k0 + tg * 2];
                const __nv_bfloat16* q1 = q0 + 8 * CPITCH;
                alo[mi][0] = *(const uint32_t*)q0;
                alo[mi][1] = *(const uint32_t*)q1;
                alo[mi][2] = *(const uint32_t*)(q0 + 8);
                alo[mi][3] = *(const uint32_t*)(q1 + 8);
            }
#pragma unroll
            for (int ni = 0; ni < 4; ni++) {
                int nr = warp_n * 32 + ni * 8 + g;
                const __nv_bfloat16* p = &sm[OFF_BHI + nr * CPITCH + k0 + tg * 2];
                bhi[ni][0] = *(const uint32_t*)p;
                bhi[ni][1] = *(const uint32_t*)(p + 8);
                const __nv_bfloat16* q = &sm[OFF_BLO + nr * CPITCH + k0 + tg * 2];
                blo[ni][0] = *(const uint32_t*)q;
                blo[ni][1] = *(const uint32_t*)(q + 8);
            }
#pragma unroll
            for (int mi = 0; mi < 4; mi++)
#pragma unroll
                for (int ni = 0; ni < 4; ni++) {
                    mma16816(acc[mi][ni], ahi[mi], bhi[ni]);
                    mma16816(acc[mi][ni], ahi[mi], blo[ni]);
                    mma16816(acc[mi][ni], alo[mi], bhi[ni]);
                }
        }
        __syncthreads();
    }

    // ---- epilogue: c0:(g, tg*2) c1:(g, tg*2+1) c2:(g+8, tg*2) c3:(g+8, tg*2+1) ----
#pragma unroll
    for (int mi = 0; mi < 4; mi++) {
        int m = m0 + warp_m * 64 + mi * 16 + g;
        float bs0 = bias[m], bs1 = bias[m + 8];
        size_t row0 = (((size_t)bI * M + m) << 9) + l0;
        size_t row1 = (((size_t)bI * M + m + 8) << 9) + l0;
#pragma unroll
        for (int ni = 0; ni < 4; ni++) {
            int ncol = warp_n * 32 + ni * 8 + tg * 2;
            float2 v0 = make_float2(acc[mi][ni][0] + bs0, acc[mi][ni][1] + bs0);
            float2 v1 = make_float2(acc[mi][ni][2] + bs1, acc[mi][ni][3] + bs1);
            if (res) {
                float2 r0 = *(const float2*)&res[row0 + ncol];
                float2 r1 = *(const float2*)&res[row1 + ncol];
                v0.x += r0.x; v0.y += r0.y; v1.x += r1.x; v1.y += r1.y;
            }
            *(float2*)&Y[row0 + ncol] = v0;
            *(float2*)&Y[row1 + ncol] = v1;
        }
    }
}

// ================= unified 64x64-tile SIMT GEMM (qkv/proj/logits) =================
#define AROW 0
#define AXT 1
#define BROW 0
#define CROW 0
#define CTRANS 2

template<int AM,int BM,int CM>
__global__ void gemm64(const float* __restrict__ A, const float* __restrict__ Bm,
                       const float* __restrict__ bias, const float* __restrict__ res,
                       float* __restrict__ Cm, int M, int N, int K) {
    __shared__ float As[16][64];
    __shared__ float Bs[16][64];
    int tid = threadIdx.x;          // 128
    int m0 = blockIdx.y * 64, n0 = blockIdx.x * 64;
    int tx = tid & 15, ty = tid >> 4;
    float ar[8], br[8];
    float acc[8][4] = {};
    int nk = K >> 4;

    auto loadA = [&](int k0) {
        if (AM == AROW) {
            int am = tid >> 1, ak = (tid & 1) * 8;
            const float* p = A + (size_t)(m0 + am) * K + k0 + ak;
            float4 v0 = *(const float4*)p;
            float4 v1 = *(const float4*)(p + 4);
            ar[0]=v0.x; ar[1]=v0.y; ar[2]=v0.z; ar[3]=v0.w;
            ar[4]=v1.x; ar[5]=v1.y; ar[6]=v1.z; ar[7]=v1.w;
        } else {
            int am = (tid & 15) * 4, ak = tid >> 4;
            int mm = m0 + am; int bI = mm >> 9, l = mm & 511;
            const float* p = A + ((size_t)(bI * CC + k0 + ak) << 9) + l;
            float4 v0 = *(const float4*)p;
            float4 v1 = *(const float4*)(p + ((size_t)8 << 9));
            ar[0]=v0.x; ar[1]=v0.y; ar[2]=v0.z; ar[3]=v0.w;
            ar[4]=v1.x; ar[5]=v1.y; ar[6]=v1.z; ar[7]=v1.w;
        }
    };
    auto stsA = [&]() {
        if (AM == AROW) {
            int am = tid >> 1, ak = (tid & 1) * 8;
#pragma unroll
            for (int j = 0; j < 8; j++) As[ak + j][am] = ar[j];
        } else {
            int am = (tid & 15) * 4, ak = tid >> 4;
            *(float4*)&As[ak][am]     = make_float4(ar[0], ar[1], ar[2], ar[3]);
            *(float4*)&As[ak + 8][am] = make_float4(ar[4], ar[5], ar[6], ar[7]);
        }
    };
    auto loadB = [&](int k0) {
        int bk = tid >> 4, bn = (tid & 15) * 4;
        const float* p = Bm + (size_t)(k0 + bk) * N + n0 + bn;
        float4 v0 = *(const float4*)p;
        float4 v1 = *(const float4*)(p + (size_t)8 * N);
        br[0]=v0.x; br[1]=v0.y; br[2]=v0.z; br[3]=v0.w;
        br[4]=v1.x; br[5]=v1.y; br[6]=v1.z; br[7]=v1.w;
    };
    auto stsB = [&]() {
        int bk = tid >> 4, bn = (tid & 15) * 4;
        *(float4*)&Bs[bk][bn]     = make_float4(br[0], br[1], br[2], br[3]);
        *(float4*)&Bs[bk + 8][bn] = make_float4(br[4], br[5], br[6], br[7]);
    };

    loadA(0); loadB(0);
    for (int kt = 0; kt < nk; kt++) {
        __syncthreads();
        stsA(); stsB();
        __syncthreads();
        if (kt + 1 < nk) { loadA((kt + 1) << 4); loadB((kt + 1) << 4); }
#pragma unroll
        for (int kk = 0; kk < 16; kk++) {
            float4 a0 = *(const float4*)&As[kk][ty * 8];
            float4 a1 = *(const float4*)&As[kk][ty * 8 + 4];
            float4 bv = *(const float4*)&Bs[kk][tx * 4];
            float a[8] = {a0.x, a0.y, a0.z, a0.w, a1.x, a1.y, a1.z, a1.w};
            float bb[4] = {bv.x, bv.y, bv.z, bv.w};
#pragma unroll
            for (int i = 0; i < 8; i++)
#pragma unroll
                for (int j = 0; j < 4; j++) acc[i][j] = fmaf(a[i], bb[j], acc[i][j]);
        }
    }

    if (CM == CROW) {
        float bj[4] = {0.f, 0.f, 0.f, 0.f};
        if (bias) {
#pragma unroll
            for (int j = 0; j < 4; j++) bj[j] = bias[n0 + tx * 4 + j];
        }
#pragma unroll
        for (int i = 0; i < 8; i++) {
            int m = m0 + ty * 8 + i;
            *(float4*)&Cm[(size_t)m * N + n0 + tx * 4] =
                make_float4(acc[i][0] + bj[0], acc[i][1] + bj[1],
                            acc[i][2] + bj[2], acc[i][3] + bj[3]);
        }
    } else {  // CTRANS
        int mbase = m0 + ty * 8; int bI = mbase >> 9, l = mbase & 511;
#pragma unroll
        for (int j = 0; j < 4; j++) {
            int n = n0 + tx * 4 + j;
            float bs = bias ? bias[n] : 0.f;
            size_t oi = (((size_t)bI * N + n) << 9) + l;
            *(float4*)&Cm[oi] = make_float4(acc[0][j] + bs, acc[1][j] + bs,
                                            acc[2][j] + bs, acc[3][j] + bs);
            *(float4*)&Cm[oi + 4] = make_float4(acc[4][j] + bs, acc[5][j] + bs,
                                                acc[6][j] + bs, acc[7][j] + bs);
        }
    }
}

// ---------------- GroupNorm (+optional emb add) + GELU, fused ----------------
__global__ void gn_gelu_kernel(const float* __restrict__ xin, const float* __restrict__ emb,
                               const float* __restrict__ scale, const float* __restrict__ bias,
                               float* __restrict__ x1_out, float* __restrict__ h_out) {
    int b = blockIdx.x >> 5;
    int g = blockIdx.x & 31;
    size_t base = ((size_t)b * CC + g * CPG) * LL;
    __shared__ float vals[CPG * LL];
    __shared__ float red[256];
    int tid = threadIdx.x;
    float s = 0.f, s2 = 0.f;
#pragma unroll
    for (int i = 0; i < 16; i++) {
        int j = tid + i * 256;
        float v = xin[base + j];
        if (emb) v += emb[base + j];
        vals[j] = v;
        s += v;
        s2 = fmaf(v, v, s2);
    }
    red[tid] = s; __syncthreads();
    for (int o = 128; o > 0; o >>= 1) { if (tid < o) red[tid] += red[tid + o]; __syncthreads(); }
    float mean = red[0] * (1.f / 4096.f);
    __syncthreads();
    red[tid] = s2; __syncthreads();
    for (int o = 128; o > 0; o >>= 1) { if (tid < o) red[tid] += red[tid + o]; __syncthreads(); }
    float var = red[0] * (1.f / 4096.f) - mean * mean;
    float rsig = rsqrtf(var + 1e-5f);
#pragma unroll
    for (int i = 0; i < 16; i++) {
        int j = tid + i * 256;
        int c = g * CPG + (j >> 9);
        float v = vals[j];
        if (x1_out) x1_out[base + j] = v;
        float nn = (v - mean) * rsig * scale[c] + bias[c];
        h_out[base + j] = gelu_exact(nn);
    }
}

// ---------------- qkv split: t(B,L,768) -> Q,K,V (B,H,L,DH) ----------------
__global__ void qkv_split_kernel(const float* __restrict__ t, float* __restrict__ Q,
                                 float* __restrict__ K, float* __restrict__ V) {
    int idx = blockIdx.x * 256 + threadIdx.x;
    int d = idx & 31;
    int l = (idx >> 5) & 511;
    int h = (idx >> 14) & 7;
    int b = idx >> 17;
    size_t base = ((size_t)(b * LL + l)) * 768 + (size_t)(d * NH + h) * 3;
    int o = ((b * NH + h) * LL + l) * DH + d;
    Q[o] = t[base];
    K[o] = t[base + 1];
    V[o] = t[base + 2];
}

// ---------------- scores S[bh,q,k] = Q.K / sqrt(DH) ----------------
__global__ void attn_score_kernel(const float* __restrict__ Q, const float* __restrict__ K,
                                  float* __restrict__ S) {
    int bh = blockIdx.z;
    int q0 = blockIdx.y * 64, k0 = blockIdx.x * 64;
    __shared__ float Qs[64][33];
    __shared__ float Ks[64][33];
    int tid = threadIdx.x;
#pragma unroll
    for (int i = 0; i < 8; i++) {
        int idx = tid + i * 256;
        int r = idx >> 5, d = idx & 31;
        Qs[r][d] = Q[((size_t)(bh << 9) + q0 + r) * 32 + d];
        Ks[r][d] = K[((size_t)(bh << 9) + k0 + r) * 32 + d];
    }
    __syncthreads();
    int tx = tid & 15, ty = tid >> 4;
    float acc[4][4] = {};
#pragma unroll
    for (int kk = 0; kk < 32; kk++) {
        float a[4], bq[4];
#pragma unroll
        for (int i = 0; i < 4; i++) a[i] = Qs[ty * 4 + i][kk];
#pragma unroll
        for (int j = 0; j < 4; j++) bq[j] = Ks[tx * 4 + j][kk];
#pragma unroll
        for (int i = 0; i < 4; i++)
#pragma unroll
            for (int j = 0; j < 4; j++) acc[i][j] = fmaf(a[i], bq[j], acc[i][j]);
    }
    const float sc = 0.17677669529663687f;
    size_t base = (size_t)bh << 18;
#pragma unroll
    for (int i = 0; i < 4; i++)
#pragma unroll
        for (int j = 0; j < 4; j++)
            S[base + (size_t)(q0 + ty * 4 + i) * 512 + k0 + tx * 4 + j] = acc[i][j] * sc;
}

// ---------------- softmax over rows of 512 ----------------
__global__ void softmax512_kernel(float* __restrict__ S) {
    size_t row = blockIdx.x;
    float* p = S + row * 512;
    int tid = threadIdx.x;       // 128
    __shared__ float red[128];
    float v[4];
#pragma unroll
    for (int i = 0; i < 4; i++) v[i] = p[tid + i * 128];
    float m = fmaxf(fmaxf(v[0], v[1]), fmaxf(v[2], v[3]));
    red[tid] = m; __syncthreads();
    for (int o = 64; o > 0; o >>= 1) { if (tid < o) red[tid] = fmaxf(red[tid], red[tid + o]); __syncthreads(); }
    m = red[0]; __syncthreads();
    float s = 0.f;
#pragma unroll
    for (int i = 0; i < 4; i++) { v[i] = expf(v[i] - m); s += v[i]; }
    red[tid] = s; __syncthreads();
    for (int o = 64; o > 0; o >>= 1) { if (tid < o) red[tid] += red[tid + o]; __syncthreads(); }
    float inv = 1.f / red[0];
#pragma unroll
    for (int i = 0; i < 4; i++) p[tid + i * 128] = v[i] * inv;
}

// ---------------- O = P @ V, write as oc[b,l, d*H + h] ----------------
__global__ void attn_av_kernel(const float* __restrict__ S, const float* __restrict__ V,
                               float* __restrict__ OCb) {
    int bh = blockIdx.y;
    int q0 = blockIdx.x * 64;
    int b = bh >> 3, h = bh & 7;
    __shared__ float Ps[64][65];
    __shared__ float Vs[64][32];
    int tid = threadIdx.x;
    int d = tid & 31, qg = tid >> 5;
    float acc[8] = {};
    for (int k0 = 0; k0 < 512; k0 += 64) {
#pragma unroll
        for (int i = 0; i < 16; i++) {
            int idx = tid + i * 256;
            int r = idx >> 6, c = idx & 63;
            Ps[r][c] = S[((size_t)bh << 18) + (size_t)(q0 + r) * 512 + k0 + c];
        }
#pragma unroll
        for (int i = 0; i < 8; i++) {
            int idx = tid + i * 256;
            int r = idx >> 5, c = idx & 31;
            Vs[r][c] = V[((size_t)(bh << 9) + k0 + r) * 32 + c];
        }
        __syncthreads();
#pragma unroll
        for (int kk = 0; kk < 64; kk++) {
            float vv = Vs[kk][d];
#pragma unroll
            for (int j = 0; j < 8; j++) acc[j] = fmaf(Ps[qg + j * 8][kk], vv, acc[j]);
        }
        __syncthreads();
    }
#pragma unroll
    for (int j = 0; j < 8; j++) {
        int q = q0 + qg + j * 8;
        OCb[((size_t)(b << 9) + q) * 256 + d * NH + h] = acc[j];
    }
}

// ---------------- MoE gating ----------------
__global__ void gating_kernel(const float* __restrict__ logits, float* __restrict__ raw,
                              float* __restrict__ g1, int* __restrict__ i1,
                              float* __restrict__ g2, int* __restrict__ i2) {
    int row = blockIdx.x;
    int tid = threadIdx.x;    // 256
    const float* p = logits + (size_t)row * EE;
    float lv[4];
#pragma unroll
    for (int j = 0; j < 4; j++) lv[j] = p[tid * 4 + j];
    __shared__ float sv[256];
    __shared__ int si[256];
    float bv = lv[0]; int bi = tid * 4;
#pragma unroll
    for (int j = 1; j < 4; j++) if (lv[j] > bv) { bv = lv[j]; bi = tid * 4 + j; }
    sv[tid] = bv; si[tid] = bi; __syncthreads();
    for (int o = 128; o > 0; o >>= 1) {
        if (tid < o) {
            if (sv[tid + o] > sv[tid] || (sv[tid + o] == sv[tid] && si[tid + o] < si[tid])) {
                sv[tid] = sv[tid + o]; si[tid] = si[tid + o];
            }
        }
        __syncthreads();
    }
    float maxv = sv[0]; int maxi = si[0];
    __syncthreads();
    float s = 0.f;
#pragma unroll
    for (int j = 0; j < 4; j++) s += expf(lv[j] - maxv);
    sv[tid] = s; __syncthreads();
    for (int o = 128; o > 0; o >>= 1) { if (tid < o) sv[tid] += sv[tid + o]; __syncthreads(); }
    float inv = 1.f / sv[0];
#pragma unroll
    for (int j = 0; j < 4; j++)
        raw[(size_t)row * EE + tid * 4 + j] = expf(lv[j] - maxv) * inv;
    __syncthreads();
    bv = -3.4e38f; bi = 0;
#pragma unroll
    for (int j = 0; j < 4; j++) {
        int e = tid * 4 + j;
        if (e != maxi && lv[j] > bv) { bv = lv[j]; bi = e; }
    }
    sv[tid] = bv; si[tid] = bi; __syncthreads();
    for (int o = 128; o > 0; o >>= 1) {
        if (tid < o) {
            if (sv[tid + o] > sv[tid] || (sv[tid + o] == sv[tid] && si[tid + o] < si[tid])) {
                sv[tid] = sv[tid + o]; si[tid] = si[tid + o];
            }
        }
        __syncthreads();
    }
    if (tid == 0) {
        float gate1v = inv;
        float gate2v = expf(sv[0] - maxv) * inv;
        float denom = gate1v + gate2v + 1e-9f;
        g1[row] = gate1v / denom;
        i1[row] = maxi;
        g2[row] = gate2v / denom;
        i2[row] = si[0];
    }
}

// ---------------- per-(b,e) sum of raw over tokens ----------------
__global__ void rawsum_kernel(const float* __restrict__ raw, float* __restrict__ rawsum) {
    int b = blockIdx.x >> 2;
    int chunk = blockIdx.x & 3;
    int e = chunk * 256 + threadIdx.x;
    const float* p = raw + (size_t)b * NTOK * EE + e;
    float s = 0.f;
    for (int n = 0; n < NTOK; n++) s += p[(size_t)n * EE];
    rawsum[b * EE + e] = s;
}

// ---------------- routing with capacity ----------------
__global__ void routing_kernel(const int* __restrict__ idx1, const float* __restrict__ gate1,
                               const int* __restrict__ idx2, const float* __restrict__ gate2,
                               int* __restrict__ slot_tok, float* __restrict__ slot_gate,
                               float* __restrict__ cnt1_out) {
    int b = blockIdx.x;
    int tid = threadIdx.x;
    __shared__ int cnt[EE];
    __shared__ int mcnt[EE];
    for (int e = tid; e < EE; e += 256) cnt[e] = 0;
    for (int i = tid; i < EE * CAPP; i += 256) {
        slot_tok[b * EE * CAPP + i] = -1;
        slot_gate[b * EE * CAPP + i] = 0.f;
    }
    __syncthreads();
    if (tid == 0) {
        for (int n = 0; n < NTOK; n++) {
            int e = idx1[b * NTOK + n];
            int pcur = cnt[e]++;
            if (pcur < CAPP) {
                slot_tok[(b * EE + e) * CAPP + pcur] = n;
                slot_gate[(b * EE + e) * CAPP + pcur] = gate1[b * NTOK + n];
            }
        }
    }
    __syncthreads();
    for (int e = tid; e < EE; e += 256) {
        cnt1_out[b * EE + e] = (float)cnt[e];
        mcnt[e] = cnt[e] < CAPP ? cnt[e] : CAPP;
        cnt[e] = 0;
    }
    __syncthreads();
    if (tid == 0) {
        for (int n = 0; n < NTOK; n++) {
            int e = idx2[b * NTOK + n];
            int pcur = mcnt[e] + cnt[e];
            cnt[e]++;
            if (pcur < CAPP) {
                slot_tok[(b * EE + e) * CAPP + pcur] = n;
                slot_gate[(b * EE + e) * CAPP + pcur] = gate2[b * NTOK + n];
            }
        }
    }
}

// ---------------- expert FFN ----------------
__global__ void expert_kernel(const float* __restrict__ xm, const float* __restrict__ w1,
                              const float* __restrict__ w2,
                              const int* __restrict__ slot_tok, const float* __restrict__ slot_gate,
                              float* __restrict__ out) {
    int e = blockIdx.x;
    int tid = threadIdx.x;    // 256
    extern __shared__ float sw[];          // 64 KB
    __shared__ float hsh[32][33];
    __shared__ int stok[32];
    __shared__ float sgate[32];
    __shared__ int s_any;
    if (tid < 32) {
        int b = tid >> 2, c = tid & 3;
        stok[tid]  = slot_tok [(b * EE + e) * CAPP + c];
        sgate[tid] = slot_gate[(b * EE + e) * CAPP + c];
    }
    if (tid == 0) s_any = 0;
    __syncthreads();
    if (tid == 0) {
        int a = 0;
        for (int i = 0; i < 32; i++) a |= (stok[i] >= 0);
        s_any = a;
    }
    __syncthreads();
    if (!s_any) return;
    const float* w1e = w1 + (size_t)e * DTOK * HIDD;
#pragma unroll
    for (int i = 0; i < 64; i++) sw[tid + i * 256] = w1e[tid + i * 256];
    __syncthreads();
    int hid = tid & 31;
#pragma unroll
    for (int pass = 0; pass < 4; pass++) {
        int sidx = pass * 8 + (tid >> 5);
        int tok = stok[sidx];
        float acc = 0.f;
        if (tok >= 0) {
            const float* xr = xm + ((size_t)((sidx >> 2) * NTOK + tok)) * DTOK;
            for (int dd = 0; dd < DTOK; dd++) acc = fmaf(xr[dd], sw[dd * HIDD + hid], acc);
        }
        hsh[sidx][hid] = gelu_exact(acc);
    }
    __syncthreads();
    const float* w2e = w2 + (size_t)e * HIDD * DTOK;
#pragma unroll
    for (int i = 0; i < 64; i++) sw[tid + i * 256] = w2e[tid + i * 256];
    __syncthreads();
#pragma unroll
    for (int i = 0; i < 64; i++) {
        int idx = tid + i * 256;
        int sidx = idx >> 9;
        int dd = idx & 511;
        int tok = stok[sidx];
        float g = sgate[sidx];
        if (tok >= 0 && g != 0.f) {
            float acc = 0.f;
#pragma unroll
            for (int h2 = 0; h2 < HIDD; h2++) acc = fmaf(hsh[sidx][h2], sw[h2 * DTOK + dd], acc);
            atomicAdd(&out[((size_t)((sidx >> 2) * NTOK + tok)) * DTOK + dd], g * acc);
        }
    }
}

// ---------------- aux loss ----------------
__global__ void loss_kernel(const float* __restrict__ rawsum, const float* __restrict__ cnt1,
                            float* __restrict__ out_scalar) {
    __shared__ float red[256];
    int tid = threadIdx.x;
    float s = 0.f;
    for (int i = tid; i < BB * EE; i += 256) s += rawsum[i] * cnt1[i];
    red[tid] = s; __syncthreads();
    for (int o = 128; o > 0; o >>= 1) { if (tid < o) red[tid] += red[tid + o]; __syncthreads(); }
    if (tid == 0) out_scalar[0] = red[0] * 1.953125e-05f;
}

// ---------------- maxpool k=3 s=2 pad=1 ----------------
__global__ void maxpool_kernel(const float* __restrict__ yf, float* __restrict__ out) {
    int idx = blockIdx.x * 256 + threadIdx.x;
    int j = idx & 255;
    int o = (idx >> 8) & 511;
    int b = idx >> 17;
    const float* row = yf + ((size_t)(b * 512 + o)) * 512;
    int l = 2 * j;
    float m = row[l];
    if (l > 0) m = fmaxf(m, row[l - 1]);
    m = fmaxf(m, row[l + 1]);
    out[idx] = m;
}

// ---------------- host orchestration ----------------
extern "C" void kernel_launch(void* const* d_in, const int* in_sizes, int n_in,
                              void* d_out, int out_size) {
    const float* x        = (const float*)d_in[0];
    const float* emb      = (const float*)d_in[1];
    const float* rb1_g1s  = (const float*)d_in[2];
    const float* rb1_g1b  = (const float*)d_in[3];
    const float* rb1_c1w  = (const float*)d_in[4];
    const float* rb1_c1b  = (const float*)d_in[5];
    const float* rb1_g2s  = (const float*)d_in[6];
    const float* rb1_g2b  = (const float*)d_in[7];
    const float* rb1_c2w  = (const float*)d_in[8];
    const float* rb1_c2b  = (const float*)d_in[9];
    const float* rb2_g1s  = (const float*)d_in[10];
    const float* rb2_g1b  = (const float*)d_in[11];
    const float* rb2_c1w  = (const float*)d_in[12];
    const float* rb2_c1b  = (const float*)d_in[13];
    const float* rb2_g2s  = (const float*)d_in[14];
    const float* rb2_g2b  = (const float*)d_in[15];
    const float* rb2_c2w  = (const float*)d_in[16];
    const float* rb2_c2b  = (const float*)d_in[17];
    const float* attn_w1  = (const float*)d_in[18];
    const float* attn_b1  = (const float*)d_in[19];
    const float* attn_w2  = (const float*)d_in[20];
    const float* attn_b2  = (const float*)d_in[21];
    const float* moe_wg   = (const float*)d_in[22];
    const float* moe_w1   = (const float*)d_in[23];
    const float* moe_w2   = (const float*)d_in[24];
    const float* out_w    = (const float*)d_in[25];
    const float* out_b    = (const float*)d_in[26];
    float* out = (float*)d_out;

    float *px1, *ph, *pr, *pxa, *pt, *pq, *pk, *pv, *ps, *poc, *pxb, *pxm;
    float *plog, *praw, *pg1, *pg2, *prs, *pc1, *psg, *pmo, *pyf;
    int *pi1, *pi2, *pst;
    cudaGetSymbolAddress((void**)&px1, g_x1);
    cudaGetSymbolAddress((void**)&ph,  g_h);
    cudaGetSymbolAddress((void**)&pr,  g_r);
    cudaGetSymbolAddress((void**)&pxa, g_xa);
    cudaGetSymbolAddress((void**)&pt,  g_t);
    cudaGetSymbolAddress((void**)&pq,  g_q);
    cudaGetSymbolAddress((void**)&pk,  g_k);
    cudaGetSymbolAddress((void**)&pv,  g_v);
    cudaGetSymbolAddress((void**)&ps,  g_s);
    cudaGetSymbolAddress((void**)&poc, g_oc);
    cudaGetSymbolAddress((void**)&pxb, g_xb);
    cudaGetSymbolAddress((void**)&pxm, g_xm);
    cudaGetSymbolAddress((void**)&plog, g_logits);
    cudaGetSymbolAddress((void**)&praw, g_raw);
    cudaGetSymbolAddress((void**)&pg1, g_gate1);
    cudaGetSymbolAddress((void**)&pg2, g_gate2);
    cudaGetSymbolAddress((void**)&pi1, g_i1);
    cudaGetSymbolAddress((void**)&pi2, g_i2);
    cudaGetSymbolAddress((void**)&prs, g_rawsum);
    cudaGetSymbolAddress((void**)&pc1, g_cnt1);
    cudaGetSymbolAddress((void**)&pst, g_slot_tok);
    cudaGetSymbolAddress((void**)&psg, g_slot_gate);
    cudaGetSymbolAddress((void**)&pmo, g_moeout);
    cudaGetSymbolAddress((void**)&pyf, g_yfull);

    cudaFuncSetAttribute(expert_kernel, cudaFuncAttributeMaxDynamicSharedMemorySize, 65536);
    cudaFuncSetAttribute(conv_mma_kernel, cudaFuncAttributeMaxDynamicSharedMemorySize, CONV_SMEM);

    // ---- res block 1 ----
    gn_gelu_kernel<<<BB * NG, 256>>>(x, emb, rb1_g1s, rb1_g1b, px1, ph);
    conv_mma_kernel<<<dim3(32, 2), 256, CONV_SMEM>>>(rb1_c1w, ph, rb1_c1b, nullptr, pr, 256);
    gn_gelu_kernel<<<BB * NG, 256>>>(pr, nullptr, rb1_g2s, rb1_g2b, nullptr, ph);
    conv_mma_kernel<<<dim3(32, 2), 256, CONV_SMEM>>>(rb1_c2w, ph, rb1_c2b, px1, pxa, 256);

    // ---- attention (transpose fused into GEMMs) ----
    gemm64<AXT,BROW,CROW><<<dim3(12, 64), 128>>>(pxa, attn_w1, attn_b1, nullptr, pt, 4096, 768, 256);
    qkv_split_kernel<<<4096, 256>>>(pt, pq, pk, pv);
    attn_score_kernel<<<dim3(8, 8, 64), 256>>>(pq, pk, ps);
    softmax512_kernel<<<64 * 512, 128>>>(ps);
    attn_av_kernel<<<dim3(8, 64), 256>>>(ps, pv, poc);
    gemm64<AROW,BROW,CTRANS><<<dim3(4, 64), 128>>>(poc, attn_w2, attn_b2, nullptr, pxb, 4096, 256, 256);

    // ---- res block 2 ----
    gn_gelu_kernel<<<BB * NG, 256>>>(pxb, emb, rb2_g1s, rb2_g1b, px1, ph);
    conv_mma_kernel<<<dim3(32, 2), 256, CONV_SMEM>>>(rb2_c1w, ph, rb2_c1b, nullptr, pr, 256);
    gn_gelu_kernel<<<BB * NG, 256>>>(pr, nullptr, rb2_g2s, rb2_g2b, nullptr, ph);
    conv_mma_kernel<<<dim3(32, 2), 256, CONV_SMEM>>>(rb2_c2w, ph, rb2_c2b, px1, pxm, 256);

    // ---- MoE ----
    gemm64<AROW,BROW,CROW><<<dim3(16, 32), 128>>>(pxm, moe_wg, nullptr, nullptr, plog, 2048, 1024, 512);
    gating_kernel<<<2048, 256>>>(plog, praw, pg1, pi1, pg2, pi2);
    rawsum_kernel<<<32, 256>>>(praw, prs);
    routing_kernel<<<BB, 256>>>(pi1, pg1, pi2, pg2, pst, psg, pc1);
    cudaMemsetAsync(pmo, 0, sizeof(float) * BB * CC * LL);
    expert_kernel<<<EE, 256, 65536>>>(pxm, moe_w1, moe_w2, pst, psg, pmo);
    loss_kernel<<<1, 256>>>(prs, pc1, out + 2097152);

    // ---- output conv + maxpool ----
    conv_mma_kernel<<<dim3(32, 4), 256, CONV_SMEM>>>(out_w, pmo, out_b, nullptr, pyf, 512);
    maxpool_kernel<<<4096, 256>>>(pyf, out);

    // second output: moe result x (B,C,L)
    cudaMemcpyAsync(out + 1048576, pmo, sizeof(float) * BB * CC * LL, cudaMemcpyDeviceToDevice);
}

// round 8
// speedup vs baseline: 1.1673x; 1.1673x over previous
#include <cuda_runtime.h>
#include <cuda_bf16.h>
#include <math.h>
#include <stdint.h>

// ---------------- problem constants ----------------
#define BB   8
#define CC   256
#define LL   512
#define NG   32      // groups
#define CPG  8       // channels per group
#define NH   8       // heads
#define DH   32      // head dim
#define EE   1024    // experts
#define HIDD 32
#define CAPP 4
#define NTOK 256     // tokens per batch for MoE (=C)
#define DTOK 512     // token dim for MoE (=L)

// ---------------- scratch (device globals; allocation-free) ----------------
__device__ float g_x1[BB*CC*LL];
__device__ float g_r [BB*CC*LL];
__device__ float g_xa[BB*CC*LL];
__device__ float g_t [BB*LL*3*CC];
__device__ float g_q [BB*NH*LL*DH];
__device__ float g_k [BB*NH*LL*DH];
__device__ float g_v [BB*NH*LL*DH];
__device__ float g_s [(size_t)BB*NH*LL*LL];
__device__ float g_oc[BB*LL*CC];
__device__ float g_xb[BB*CC*LL];
__device__ float g_xm[BB*CC*LL];
__device__ float g_logits[BB*NTOK*EE];
__device__ float g_raw  [BB*NTOK*EE];
__device__ float g_gate1[BB*NTOK];
__device__ float g_gate2[BB*NTOK];
__device__ int   g_i1[BB*NTOK];
__device__ int   g_i2[BB*NTOK];
__device__ float g_rawsum[BB*EE];
__device__ float g_cnt1 [BB*EE];
__device__ int   g_slot_tok [BB*EE*CAPP];
__device__ float g_slot_gate[BB*EE*CAPP];
__device__ float g_moeout[BB*CC*LL];
__device__ float g_yfull[(size_t)BB*2*CC*LL];
// bf16 hi/lo operand buffers
#define WTOT (4*196608 + 393216)
__device__ unsigned short g_whi[WTOT];
__device__ unsigned short g_wlo[WTOT];
__device__ unsigned short g_hhi[BB*CC*LL];
__device__ unsigned short g_hlo[BB*CC*LL];

__device__ __forceinline__ float gelu_exact(float v) {
    return 0.5f * v * (1.0f + erff(v * 0.7071067811865476f));
}
__device__ __forceinline__ void split_bf16(float v, unsigned short& h, unsigned short& l) {
    __nv_bfloat16 hb = __float2bfloat16(v);
    __nv_bfloat16 lb = __float2bfloat16(v - __bfloat162float(hb));
    h = *(unsigned short*)&hb;
    l = *(unsigned short*)&lb;
}

// ---------------- float -> bf16 hi/lo conversion ----------------
__global__ void cvt_hilo_kernel(const float* __restrict__ src, unsigned short* __restrict__ hi,
                                unsigned short* __restrict__ lo, int n) {
    int i = blockIdx.x * 256 + threadIdx.x;
    if (i < n) {
        unsigned short h, l;
        split_bf16(src[i], h, l);
        hi[i] = h; lo[i] = l;
    }
}

// ================= warp-level bf16 MMA (m16n8k16, f32 accum) =================
__device__ __forceinline__ void mma16816(float* c, const uint32_t* a, const uint32_t* b) {
    asm volatile("mma.sync.aligned.m16n8k16.row.col.f32.bf16.bf16.f32 "
        "{%0,%1,%2,%3}, {%4,%5,%6,%7}, {%8,%9}, {%0,%1,%2,%3};"
        : "+f"(c[0]), "+f"(c[1]), "+f"(c[2]), "+f"(c[3])
        : "r"(a[0]), "r"(a[1]), "r"(a[2]), "r"(a[3]), "r"(b[0]), "r"(b[1]));
}

// ================= tensor-core conv1d(k=3,pad=1): C[m][n]=sum_k W[m][k]*X[k][n] =================
// fp32 via bf16 hi/lo split (hi*hi + hi*lo + lo*hi). Operands pre-converted to bf16.
// CTA: 64m x 128n, 256 threads = 8 warps (2m x 4n), warp tile 32m x 32n.
// K = 768 in 12 chunks of 64.
#define CPITCH 72
#define OFF_AHI 0
#define OFF_ALO (64*CPITCH)
#define OFF_BHI (2*64*CPITCH)
#define OFF_BLO (2*64*CPITCH + 128*CPITCH)
#define CONV_SMEM ((2*64*CPITCH + 2*128*CPITCH) * 2)   // 55296 bytes

__global__ void __launch_bounds__(256, 2)
conv_mma_kernel(const unsigned short* __restrict__ Whi, const unsigned short* __restrict__ Wlo,
                const unsigned short* __restrict__ Xhi, const unsigned short* __restrict__ Xlo,
                const float* __restrict__ bias, const float* __restrict__ res,
                float* __restrict__ Y, int M) {
    extern __shared__ unsigned short sm[];
    int tid = threadIdx.x;
    int wid = tid >> 5, lane = tid & 31;
    int g = lane >> 2, tg = lane & 3;
    int warp_m = wid & 1, warp_n = wid >> 1;      // 2 x 4
    int n0 = blockIdx.x * 128, m0 = blockIdx.y * 64;
    int bI = n0 >> 9, l0 = n0 & 511;

    const unsigned short* Wh = Whi + (size_t)m0 * 768;
    const unsigned short* Wl = Wlo + (size_t)m0 * 768;
    const unsigned short* Xh = Xhi + (((size_t)bI * CC) << 9);
    const unsigned short* Xl = Xlo + (((size_t)bI * CC) << 9);

    float acc[2][4][4];
#pragma unroll
    for (int mi = 0; mi < 2; mi++)
#pragma unroll
        for (int ni = 0; ni < 4; ni++)
#pragma unroll
            for (int r = 0; r < 4; r++) acc[mi][ni][r] = 0.f;

    // A fill task: each thread owns (m-row, 16-k segment)
    int fa_m = tid >> 2, fa_k = (tid & 3) * 16;
    // B fill task: each thread owns (n-row, 32-k half)
    int fb_n = tid >> 1, fb_h = (tid & 1) * 32;

    for (int c = 0; c < 12; c++) {
        int c64 = c * 64;
        // ---- fill A: 64m x 64k hi/lo, vectorized 16 bf16 per array ----
        {
            const unsigned short* ph = Wh + (size_t)fa_m * 768 + c64 + fa_k;
            const unsigned short* pl = Wl + (size_t)fa_m * 768 + c64 + fa_k;
            uint4 h0 = *(const uint4*)ph;
            uint4 h1 = *(const uint4*)(ph + 8);
            uint4 l0v = *(const uint4*)pl;
            uint4 l1v = *(const uint4*)(pl + 8);
            *(uint4*)&sm[OFF_AHI + fa_m * CPITCH + fa_k]     = h0;
            *(uint4*)&sm[OFF_AHI + fa_m * CPITCH + fa_k + 8] = h1;
            *(uint4*)&sm[OFF_ALO + fa_m * CPITCH + fa_k]     = l0v;
            *(uint4*)&sm[OFF_ALO + fa_m * CPITCH + fa_k + 8] = l1v;
        }
        // ---- fill B: 128n x 64k hi/lo, conv gather with halo (pure bf16 loads) ----
        {
            int kg = c64 + fb_h;
            int ic = kg / 3, t = kg - 3 * ic;
            int l = l0 + fb_n;
            unsigned short* dh = &sm[OFF_BHI + fb_n * CPITCH + fb_h];
            unsigned short* dl = &sm[OFF_BLO + fb_n * CPITCH + fb_h];
#pragma unroll 8
            for (int i = 0; i < 32; i++) {
                int ll = l + t - 1;
                bool ok = ((unsigned)ll < 512u);
                int src = (ic << 9) + ll;
                dh[i] = ok ? Xh[src] : (unsigned short)0;
                dl[i] = ok ? Xl[src] : (unsigned short)0;
                if (++t == 3) { t = 0; ++ic; }
            }
        }
        __syncthreads();
#pragma unroll
        for (int ks = 0; ks < 4; ks++) {
            int k0 = ks * 16;
            uint32_t ahi[2][4], alo[2][4], bhi[4][2], blo[4][2];
#pragma unroll
            for (int mi = 0; mi < 2; mi++) {
                int r0 = warp_m * 32 + mi * 16 + g;
                const unsigned short* p0 = &sm[OFF_AHI + r0 * CPITCH + k0 + tg * 2];
                const unsigned short* p1 = p0 + 8 * CPITCH;
                ahi[mi][0] = *(const uint32_t*)p0;
                ahi[mi][1] = *(const uint32_t*)p1;
                ahi[mi][2] = *(const uint32_t*)(p0 + 8);
                ahi[mi][3] = *(const uint32_t*)(p1 + 8);
                const unsigned short* q0 = &sm[OFF_ALO + r0 * CPITCH + k0 + tg * 2];
                const unsigned short* q1 = q0 + 8 * CPITCH;
                alo[mi][0] = *(const uint32_t*)q0;
                alo[mi][1] = *(const uint32_t*)q1;
                alo[mi][2] = *(const uint32_t*)(q0 + 8);
                alo[mi][3] = *(const uint32_t*)(q1 + 8);
            }
#pragma unroll
            for (int ni = 0; ni < 4; ni++) {
                int nr = warp_n * 32 + ni * 8 + g;
                const unsigned short* p = &sm[OFF_BHI + nr * CPITCH + k0 + tg * 2];
                bhi[ni][0] = *(const uint32_t*)p;
                bhi[ni][1] = *(const uint32_t*)(p + 8);
                const unsigned short* q = &sm[OFF_BLO + nr * CPITCH + k0 + tg * 2];
                blo[ni][0] = *(const uint32_t*)q;
                blo[ni][1] = *(const uint32_t*)(q + 8);
            }
#pragma unroll
            for (int mi = 0; mi < 2; mi++)
#pragma unroll
                for (int ni = 0; ni < 4; ni++) {
                    mma16816(acc[mi][ni], ahi[mi], bhi[ni]);
                    mma16816(acc[mi][ni], ahi[mi], blo[ni]);
                    mma16816(acc[mi][ni], alo[mi], bhi[ni]);
                }
        }
        __syncthreads();
    }

    // ---- epilogue ----
#pragma unroll
    for (int mi = 0; mi < 2; mi++) {
        int m = m0 + warp_m * 32 + mi * 16 + g;
        float bs0 = bias[m], bs1 = bias[m + 8];
        size_t row0 = (((size_t)bI * M + m) << 9) + l0;
        size_t row1 = (((size_t)bI * M + m + 8) << 9) + l0;
#pragma unroll
        for (int ni = 0; ni < 4; ni++) {
            int ncol = warp_n * 32 + ni * 8 + tg * 2;
            float2 v0 = make_float2(acc[mi][ni][0] + bs0, acc[mi][ni][1] + bs0);
            float2 v1 = make_float2(acc[mi][ni][2] + bs1, acc[mi][ni][3] + bs1);
            if (res) {
                float2 r0 = *(const float2*)&res[row0 + ncol];
                float2 r1 = *(const float2*)&res[row1 + ncol];
                v0.x += r0.x; v0.y += r0.y; v1.x += r1.x; v1.y += r1.y;
            }
            *(float2*)&Y[row0 + ncol] = v0;
            *(float2*)&Y[row1 + ncol] = v1;
        }
    }
}

// ================= unified 64x64-tile SIMT GEMM (qkv/proj/logits) =================
#define AROW 0
#define AXT 1
#define BROW 0
#define CROW 0
#define CTRANS 2

template<int AM,int BM,int CM>
__global__ void gemm64(const float* __restrict__ A, const float* __restrict__ Bm,
                       const float* __restrict__ bias, const float* __restrict__ res,
                       float* __restrict__ Cm, int M, int N, int K) {
    __shared__ float As[16][64];
    __shared__ float Bs[16][64];
    int tid = threadIdx.x;          // 128
    int m0 = blockIdx.y * 64, n0 = blockIdx.x * 64;
    int tx = tid & 15, ty = tid >> 4;
    float ar[8], br[8];
    float acc[8][4] = {};
    int nk = K >> 4;

    auto loadA = [&](int k0) {
        if (AM == AROW) {
            int am = tid >> 1, ak = (tid & 1) * 8;
            const float* p = A + (size_t)(m0 + am) * K + k0 + ak;
            float4 v0 = *(const float4*)p;
            float4 v1 = *(const float4*)(p + 4);
            ar[0]=v0.x; ar[1]=v0.y; ar[2]=v0.z; ar[3]=v0.w;
            ar[4]=v1.x; ar[5]=v1.y; ar[6]=v1.z; ar[7]=v1.w;
        } else {
            int am = (tid & 15) * 4, ak = tid >> 4;
            int mm = m0 + am; int bI = mm >> 9, l = mm & 511;
            const float* p = A + ((size_t)(bI * CC + k0 + ak) << 9) + l;
            float4 v0 = *(const float4*)p;
            float4 v1 = *(const float4*)(p + ((size_t)8 << 9));
            ar[0]=v0.x; ar[1]=v0.y; ar[2]=v0.z; ar[3]=v0.w;
            ar[4]=v1.x; ar[5]=v1.y; ar[6]=v1.z; ar[7]=v1.w;
        }
    };
    auto stsA = [&]() {
        if (AM == AROW) {
            int am = tid >> 1, ak = (tid & 1) * 8;
#pragma unroll
            for (int j = 0; j < 8; j++) As[ak + j][am] = ar[j];
        } else {
            int am = (tid & 15) * 4, ak = tid >> 4;
            *(float4*)&As[ak][am]     = make_float4(ar[0], ar[1], ar[2], ar[3]);
            *(float4*)&As[ak + 8][am] = make_float4(ar[4], ar[5], ar[6], ar[7]);
        }
    };
    auto loadB = [&](int k0) {
        int bk = tid >> 4, bn = (tid & 15) * 4;
        const float* p = Bm + (size_t)(k0 + bk) * N + n0 + bn;
        float4 v0 = *(const float4*)p;
        float4 v1 = *(const float4*)(p + (size_t)8 * N);
        br[0]=v0.x; br[1]=v0.y; br[2]=v0.z; br[3]=v0.w;
        br[4]=v1.x; br[5]=v1.y; br[6]=v1.z; br[7]=v1.w;
    };
    auto stsB = [&]() {
        int bk = tid >> 4, bn = (tid & 15) * 4;
        *(float4*)&Bs[bk][bn]     = make_float4(br[0], br[1], br[2], br[3]);
        *(float4*)&Bs[bk + 8][bn] = make_float4(br[4], br[5], br[6], br[7]);
    };

    loadA(0); loadB(0);
    for (int kt = 0; kt < nk; kt++) {
        __syncthreads();
        stsA(); stsB();
        __syncthreads();
        if (kt + 1 < nk) { loadA((kt + 1) << 4); loadB((kt + 1) << 4); }
#pragma unroll
        for (int kk = 0; kk < 16; kk++) {
            float4 a0 = *(const float4*)&As[kk][ty * 8];
            float4 a1 = *(const float4*)&As[kk][ty * 8 + 4];
            float4 bv = *(const float4*)&Bs[kk][tx * 4];
            float a[8] = {a0.x, a0.y, a0.z, a0.w, a1.x, a1.y, a1.z, a1.w};
            float bb[4] = {bv.x, bv.y, bv.z, bv.w};
#pragma unroll
            for (int i = 0; i < 8; i++)
#pragma unroll
                for (int j = 0; j < 4; j++) acc[i][j] = fmaf(a[i], bb[j], acc[i][j]);
        }
    }

    if (CM == CROW) {
        float bj[4] = {0.f, 0.f, 0.f, 0.f};
        if (bias) {
#pragma unroll
            for (int j = 0; j < 4; j++) bj[j] = bias[n0 + tx * 4 + j];
        }
#pragma unroll
        for (int i = 0; i < 8; i++) {
            int m = m0 + ty * 8 + i;
            *(float4*)&Cm[(size_t)m * N + n0 + tx * 4] =
                make_float4(acc[i][0] + bj[0], acc[i][1] + bj[1],
                            acc[i][2] + bj[2], acc[i][3] + bj[3]);
        }
    } else {  // CTRANS
        int mbase = m0 + ty * 8; int bI = mbase >> 9, l = mbase & 511;
#pragma unroll
        for (int j = 0; j < 4; j++) {
            int n = n0 + tx * 4 + j;
            float bs = bias ? bias[n] : 0.f;
            size_t oi = (((size_t)bI * N + n) << 9) + l;
            *(float4*)&Cm[oi] = make_float4(acc[0][j] + bs, acc[1][j] + bs,
                                            acc[2][j] + bs, acc[3][j] + bs);
            *(float4*)&Cm[oi + 4] = make_float4(acc[4][j] + bs, acc[5][j] + bs,
                                                acc[6][j] + bs, acc[7][j] + bs);
        }
    }
}

// ---------------- GroupNorm (+optional emb add) + GELU, fused; bf16 hi/lo output ----------------
__global__ void gn_gelu_kernel(const float* __restrict__ xin, const float* __restrict__ emb,
                               const float* __restrict__ scale, const float* __restrict__ bias,
                               float* __restrict__ x1_out,
                               unsigned short* __restrict__ hhi, unsigned short* __restrict__ hlo) {
    int b = blockIdx.x >> 5;
    int g = blockIdx.x & 31;
    size_t base = ((size_t)b * CC + g * CPG) * LL;
    __shared__ float vals[CPG * LL];
    __shared__ float red[256];
    int tid = threadIdx.x;
    float s = 0.f, s2 = 0.f;
#pragma unroll
    for (int i = 0; i < 16; i++) {
        int j = tid + i * 256;
        float v = xin[base + j];
        if (emb) v += emb[base + j];
        vals[j] = v;
        s += v;
        s2 = fmaf(v, v, s2);
    }
    red[tid] = s; __syncthreads();
    for (int o = 128; o > 0; o >>= 1) { if (tid < o) red[tid] += red[tid + o]; __syncthreads(); }
    float mean = red[0] * (1.f / 4096.f);
    __syncthreads();
    red[tid] = s2; __syncthreads();
    for (int o = 128; o > 0; o >>= 1) { if (tid < o) red[tid] += red[tid + o]; __syncthreads(); }
    float var = red[0] * (1.f / 4096.f) - mean * mean;
    float rsig = rsqrtf(var + 1e-5f);
#pragma unroll
    for (int i = 0; i < 16; i++) {
        int j = tid + i * 256;
        int c = g * CPG + (j >> 9);
        float v = vals[j];
        if (x1_out) x1_out[base + j] = v;
        float nn = (v - mean) * rsig * scale[c] + bias[c];
        float hv = gelu_exact(nn);
        unsigned short hu, lu;
        split_bf16(hv, hu, lu);
        hhi[base + j] = hu;
        hlo[base + j] = lu;
    }
}

// ---------------- qkv split: t(B,L,768) -> Q,K,V (B,H,L,DH) ----------------
__global__ void qkv_split_kernel(const float* __restrict__ t, float* __restrict__ Q,
                                 float* __restrict__ K, float* __restrict__ V) {
    int idx = blockIdx.x * 256 + threadIdx.x;
    int d = idx & 31;
    int l = (idx >> 5) & 511;
    int h = (idx >> 14) & 7;
    int b = idx >> 17;
    size_t base = ((size_t)(b * LL + l)) * 768 + (size_t)(d * NH + h) * 3;
    int o = ((b * NH + h) * LL + l) * DH + d;
    Q[o] = t[base];
    K[o] = t[base + 1];
    V[o] = t[base + 2];
}

// ---------------- scores S[bh,q,k] = Q.K / sqrt(DH) ----------------
__global__ void attn_score_kernel(const float* __restrict__ Q, const float* __restrict__ K,
                                  float* __restrict__ S) {
    int bh = blockIdx.z;
    int q0 = blockIdx.y * 64, k0 = blockIdx.x * 64;
    __shared__ float Qs[64][33];
    __shared__ float Ks[64][33];
    int tid = threadIdx.x;
#pragma unroll
    for (int i = 0; i < 8; i++) {
        int idx = tid + i * 256;
        int r = idx >> 5, d = idx & 31;
        Qs[r][d] = Q[((size_t)(bh << 9) + q0 + r) * 32 + d];
        Ks[r][d] = K[((size_t)(bh << 9) + k0 + r) * 32 + d];
    }
    __syncthreads();
    int tx = tid & 15, ty = tid >> 4;
    float acc[4][4] = {};
#pragma unroll
    for (int kk = 0; kk < 32; kk++) {
        float a[4], bq[4];
#pragma unroll
        for (int i = 0; i < 4; i++) a[i] = Qs[ty * 4 + i][kk];
#pragma unroll
        for (int j = 0; j < 4; j++) bq[j] = Ks[tx * 4 + j][kk];
#pragma unroll
        for (int i = 0; i < 4; i++)
#pragma unroll
            for (int j = 0; j < 4; j++) acc[i][j] = fmaf(a[i], bq[j], acc[i][j]);
    }
    const float sc = 0.17677669529663687f;
    size_t base = (size_t)bh << 18;
#pragma unroll
    for (int i = 0; i < 4; i++)
#pragma unroll
        for (int j = 0; j < 4; j++)
            S[base + (size_t)(q0 + ty * 4 + i) * 512 + k0 + tx * 4 + j] = acc[i][j] * sc;
}

// ---------------- softmax over rows of 512 ----------------
__global__ void softmax512_kernel(float* __restrict__ S) {
    size_t row = blockIdx.x;
    float* p = S + row * 512;
    int tid = threadIdx.x;       // 128
    __shared__ float red[128];
    float v[4];
#pragma unroll
    for (int i = 0; i < 4; i++) v[i] = p[tid + i * 128];
    float m = fmaxf(fmaxf(v[0], v[1]), fmaxf(v[2], v[3]));
    red[tid] = m; __syncthreads();
    for (int o = 64; o > 0; o >>= 1) { if (tid < o) red[tid] = fmaxf(red[tid], red[tid + o]); __syncthreads(); }
    m = red[0]; __syncthreads();
    float s = 0.f;
#pragma unroll
    for (int i = 0; i < 4; i++) { v[i] = expf(v[i] - m); s += v[i]; }
    red[tid] = s; __syncthreads();
    for (int o = 64; o > 0; o >>= 1) { if (tid < o) red[tid] += red[tid + o]; __syncthreads(); }
    float inv = 1.f / red[0];
#pragma unroll
    for (int i = 0; i < 4; i++) p[tid + i * 128] = v[i] * inv;
}

// ---------------- O = P @ V, write as oc[b,l, d*H + h] ----------------
__global__ void attn_av_kernel(const float* __restrict__ S, const float* __restrict__ V,
                               float* __restrict__ OCb) {
    int bh = blockIdx.y;
    int q0 = blockIdx.x * 64;
    int b = bh >> 3, h = bh & 7;
    __shared__ float Ps[64][65];
    __shared__ float Vs[64][32];
    int tid = threadIdx.x;
    int d = tid & 31, qg = tid >> 5;
    float acc[8] = {};
    for (int k0 = 0; k0 < 512; k0 += 64) {
#pragma unroll
        for (int i = 0; i < 16; i++) {
            int idx = tid + i * 256;
            int r = idx >> 6, c = idx & 63;
            Ps[r][c] = S[((size_t)bh << 18) + (size_t)(q0 + r) * 512 + k0 + c];
        }
#pragma unroll
        for (int i = 0; i < 8; i++) {
            int idx = tid + i * 256;
            int r = idx >> 5, c = idx & 31;
            Vs[r][c] = V[((size_t)(bh << 9) + k0 + r) * 32 + c];
        }
        __syncthreads();
#pragma unroll
        for (int kk = 0; kk < 64; kk++) {
            float vv = Vs[kk][d];
#pragma unroll
            for (int j = 0; j < 8; j++) acc[j] = fmaf(Ps[qg + j * 8][kk], vv, acc[j]);
        }
        __syncthreads();
    }
#pragma unroll
    for (int j = 0; j < 8; j++) {
        int q = q0 + qg + j * 8;
        OCb[((size_t)(b << 9) + q) * 256 + d * NH + h] = acc[j];
    }
}

// ---------------- MoE gating ----------------
__global__ void gating_kernel(const float* __restrict__ logits, float* __restrict__ raw,
                              float* __restrict__ g1, int* __restrict__ i1,
                              float* __restrict__ g2, int* __restrict__ i2) {
    int row = blockIdx.x;
    int tid = threadIdx.x;    // 256
    const float* p = logits + (size_t)row * EE;
    float lv[4];
#pragma unroll
    for (int j = 0; j < 4; j++) lv[j] = p[tid * 4 + j];
    __shared__ float sv[256];
    __shared__ int si[256];
    float bv = lv[0]; int bi = tid * 4;
#pragma unroll
    for (int j = 1; j < 4; j++) if (lv[j] > bv) { bv = lv[j]; bi = tid * 4 + j; }
    sv[tid] = bv; si[tid] = bi; __syncthreads();
    for (int o = 128; o > 0; o >>= 1) {
        if (tid < o) {
            if (sv[tid + o] > sv[tid] || (sv[tid + o] == sv[tid] && si[tid + o] < si[tid])) {
                sv[tid] = sv[tid + o]; si[tid] = si[tid + o];
            }
        }
        __syncthreads();
    }
    float maxv = sv[0]; int maxi = si[0];
    __syncthreads();
    float s = 0.f;
#pragma unroll
    for (int j = 0; j < 4; j++) s += expf(lv[j] - maxv);
    sv[tid] = s; __syncthreads();
    for (int o = 128; o > 0; o >>= 1) { if (tid < o) sv[tid] += sv[tid + o]; __syncthreads(); }
    float inv = 1.f / sv[0];
#pragma unroll
    for (int j = 0; j < 4; j++)
        raw[(size_t)row * EE + tid * 4 + j] = expf(lv[j] - maxv) * inv;
    __syncthreads();
    bv = -3.4e38f; bi = 0;
#pragma unroll
    for (int j = 0; j < 4; j++) {
        int e = tid * 4 + j;
        if (e != maxi && lv[j] > bv) { bv = lv[j]; bi = e; }
    }
    sv[tid] = bv; si[tid] = bi; __syncthreads();
    for (int o = 128; o > 0; o >>= 1) {
        if (tid < o) {
            if (sv[tid + o] > sv[tid] || (sv[tid + o] == sv[tid] && si[tid + o] < si[tid])) {
                sv[tid] = sv[tid + o]; si[tid] = si[tid + o];
            }
        }
        __syncthreads();
    }
    if (tid == 0) {
        float gate1v = inv;
        float gate2v = expf(sv[0] - maxv) * inv;
        float denom = gate1v + gate2v + 1e-9f;
        g1[row] = gate1v / denom;
        i1[row] = maxi;
        g2[row] = gate2v / denom;
        i2[row] = si[0];
    }
}

// ---------------- per-(b,e) sum of raw over tokens ----------------
__global__ void rawsum_kernel(const float* __restrict__ raw, float* __restrict__ rawsum) {
    int b = blockIdx.x >> 2;
    int chunk = blockIdx.x & 3;
    int e = chunk * 256 + threadIdx.x;
    const float* p = raw + (size_t)b * NTOK * EE + e;
    float s = 0.f;
    for (int n = 0; n < NTOK; n++) s += p[(size_t)n * EE];
    rawsum[b * EE + e] = s;
}

// ---------------- routing with capacity ----------------
__global__ void routing_kernel(const int* __restrict__ idx1, const float* __restrict__ gate1,
                               const int* __restrict__ idx2, const float* __restrict__ gate2,
                               int* __restrict__ slot_tok, float* __restrict__ slot_gate,
                               float* __restrict__ cnt1_out) {
    int b = blockIdx.x;
    int tid = threadIdx.x;
    __shared__ int cnt[EE];
    __shared__ int mcnt[EE];
    for (int e = tid; e < EE; e += 256) cnt[e] = 0;
    for (int i = tid; i < EE * CAPP; i += 256) {
        slot_tok[b * EE * CAPP + i] = -1;
        slot_gate[b * EE * CAPP + i] = 0.f;
    }
    __syncthreads();
    if (tid == 0) {
        for (int n = 0; n < NTOK; n++) {
            int e = idx1[b * NTOK + n];
            int pcur = cnt[e]++;
            if (pcur < CAPP) {
                slot_tok[(b * EE + e) * CAPP + pcur] = n;
                slot_gate[(b * EE + e) * CAPP + pcur] = gate1[b * NTOK + n];
            }
        }
    }
    __syncthreads();
    for (int e = tid; e < EE; e += 256) {
        cnt1_out[b * EE + e] = (float)cnt[e];
        mcnt[e] = cnt[e] < CAPP ? cnt[e] : CAPP;
        cnt[e] = 0;
    }
    __syncthreads();
    if (tid == 0) {
        for (int n = 0; n < NTOK; n++) {
            int e = idx2[b * NTOK + n];
            int pcur = mcnt[e] + cnt[e];
            cnt[e]++;
            if (pcur < CAPP) {
                slot_tok[(b * EE + e) * CAPP + pcur] = n;
                slot_gate[(b * EE + e) * CAPP + pcur] = gate2[b * NTOK + n];
            }
        }
    }
}

// ---------------- expert FFN ----------------
__global__ void expert_kernel(const float* __restrict__ xm, const float* __restrict__ w1,
                              const float* __restrict__ w2,
                              const int* __restrict__ slot_tok, const float* __restrict__ slot_gate,
                              float* __restrict__ out) {
    int e = blockIdx.x;
    int tid = threadIdx.x;    // 256
    extern __shared__ float sw[];          // 64 KB
    __shared__ float hsh[32][33];
    __shared__ int stok[32];
    __shared__ float sgate[32];
    __shared__ int s_any;
    if (tid < 32) {
        int b = tid >> 2, c = tid & 3;
        stok[tid]  = slot_tok [(b * EE + e) * CAPP + c];
        sgate[tid] = slot_gate[(b * EE + e) * CAPP + c];
    }
    if (tid == 0) s_any = 0;
    __syncthreads();
    if (tid == 0) {
        int a = 0;
        for (int i = 0; i < 32; i++) a |= (stok[i] >= 0);
        s_any = a;
    }
    __syncthreads();
    if (!s_any) return;
    const float* w1e = w1 + (size_t)e * DTOK * HIDD;
#pragma unroll
    for (int i = 0; i < 64; i++) sw[tid + i * 256] = w1e[tid + i * 256];
    __syncthreads();
    int hid = tid & 31;
#pragma unroll
    for (int pass = 0; pass < 4; pass++) {
        int sidx = pass * 8 + (tid >> 5);
        int tok = stok[sidx];
        float acc = 0.f;
        if (tok >= 0) {
            const float* xr = xm + ((size_t)((sidx >> 2) * NTOK + tok)) * DTOK;
            for (int dd = 0; dd < DTOK; dd++) acc = fmaf(xr[dd], sw[dd * HIDD + hid], acc);
        }
        hsh[sidx][hid] = gelu_exact(acc);
    }
    __syncthreads();
    const float* w2e = w2 + (size_t)e * HIDD * DTOK;
#pragma unroll
    for (int i = 0; i < 64; i++) sw[tid + i * 256] = w2e[tid + i * 256];
    __syncthreads();
#pragma unroll
    for (int i = 0; i < 64; i++) {
        int idx = tid + i * 256;
        int sidx = idx >> 9;
        int dd = idx & 511;
        int tok = stok[sidx];
        float g = sgate[sidx];
        if (tok >= 0 && g != 0.f) {
            float acc = 0.f;
#pragma unroll
            for (int h2 = 0; h2 < HIDD; h2++) acc = fmaf(hsh[sidx][h2], sw[h2 * DTOK + dd], acc);
            atomicAdd(&out[((size_t)((sidx >> 2) * NTOK + tok)) * DTOK + dd], g * acc);
        }
    }
}

// ---------------- aux loss ----------------
__global__ void loss_kernel(const float* __restrict__ rawsum, const float* __restrict__ cnt1,
                            float* __restrict__ out_scalar) {
    __shared__ float red[256];
    int tid = threadIdx.x;
    float s = 0.f;
    for (int i = tid; i < BB * EE; i += 256) s += rawsum[i] * cnt1[i];
    red[tid] = s; __syncthreads();
    for (int o = 128; o > 0; o >>= 1) { if (tid < o) red[tid] += red[tid + o]; __syncthreads(); }
    if (tid == 0) out_scalar[0] = red[0] * 1.953125e-05f;
}

// ---------------- maxpool k=3 s=2 pad=1 ----------------
__global__ void maxpool_kernel(const float* __restrict__ yf, float* __restrict__ out) {
    int idx = blockIdx.x * 256 + threadIdx.x;
    int j = idx & 255;
    int o = (idx >> 8) & 511;
    int b = idx >> 17;
    const float* row = yf + ((size_t)(b * 512 + o)) * 512;
    int l = 2 * j;
    float m = row[l];
    if (l > 0) m = fmaxf(m, row[l - 1]);
    m = fmaxf(m, row[l + 1]);
    out[idx] = m;
}

// ---------------- host orchestration ----------------
extern "C" void kernel_launch(void* const* d_in, const int* in_sizes, int n_in,
                              void* d_out, int out_size) {
    const float* x        = (const float*)d_in[0];
    const float* emb      = (const float*)d_in[1];
    const float* rb1_g1s  = (const float*)d_in[2];
    const float* rb1_g1b  = (const float*)d_in[3];
    const float* rb1_c1w  = (const float*)d_in[4];
    const float* rb1_c1b  = (const float*)d_in[5];
    const float* rb1_g2s  = (const float*)d_in[6];
    const float* rb1_g2b  = (const float*)d_in[7];
    const float* rb1_c2w  = (const float*)d_in[8];
    const float* rb1_c2b  = (const float*)d_in[9];
    const float* rb2_g1s  = (const float*)d_in[10];
    const float* rb2_g1b  = (const float*)d_in[11];
    const float* rb2_c1w  = (const float*)d_in[12];
    const float* rb2_c1b  = (const float*)d_in[13];
    const float* rb2_g2s  = (const float*)d_in[14];
    const float* rb2_g2b  = (const float*)d_in[15];
    const float* rb2_c2w  = (const float*)d_in[16];
    const float* rb2_c2b  = (const float*)d_in[17];
    const float* attn_w1  = (const float*)d_in[18];
    const float* attn_b1  = (const float*)d_in[19];
    const float* attn_w2  = (const float*)d_in[20];
    const float* attn_b2  = (const float*)d_in[21];
    const float* moe_wg   = (const float*)d_in[22];
    const float* moe_w1   = (const float*)d_in[23];
    const float* moe_w2   = (const float*)d_in[24];
    const float* out_w    = (const float*)d_in[25];
    const float* out_b    = (const float*)d_in[26];
    float* out = (float*)d_out;

    float *px1, *pr, *pxa, *pt, *pq, *pk, *pv, *ps, *poc, *pxb, *pxm;
    float *plog, *praw, *pg1, *pg2, *prs, *pc1, *psg, *pmo, *pyf;
    int *pi1, *pi2, *pst;
    unsigned short *pwhi, *pwlo, *phhi, *phlo;
    cudaGetSymbolAddress((void**)&px1, g_x1);
    cudaGetSymbolAddress((void**)&pr,  g_r);
    cudaGetSymbolAddress((void**)&pxa, g_xa);
    cudaGetSymbolAddress((void**)&pt,  g_t);
    cudaGetSymbolAddress((void**)&pq,  g_q);
    cudaGetSymbolAddress((void**)&pk,  g_k);
    cudaGetSymbolAddress((void**)&pv,  g_v);
    cudaGetSymbolAddress((void**)&ps,  g_s);
    cudaGetSymbolAddress((void**)&poc, g_oc);
    cudaGetSymbolAddress((void**)&pxb, g_xb);
    cudaGetSymbolAddress((void**)&pxm, g_xm);
    cudaGetSymbolAddress((void**)&plog, g_logits);
    cudaGetSymbolAddress((void**)&praw, g_raw);
    cudaGetSymbolAddress((void**)&pg1, g_gate1);
    cudaGetSymbolAddress((void**)&pg2, g_gate2);
    cudaGetSymbolAddress((void**)&pi1, g_i1);
    cudaGetSymbolAddress((void**)&pi2, g_i2);
    cudaGetSymbolAddress((void**)&prs, g_rawsum);
    cudaGetSymbolAddress((void**)&pc1, g_cnt1);
    cudaGetSymbolAddress((void**)&pst, g_slot_tok);
    cudaGetSymbolAddress((void**)&psg, g_slot_gate);
    cudaGetSymbolAddress((void**)&pmo, g_moeout);
    cudaGetSymbolAddress((void**)&pyf, g_yfull);
    cudaGetSymbolAddress((void**)&pwhi, g_whi);
    cudaGetSymbolAddress((void**)&pwlo, g_wlo);
    cudaGetSymbolAddress((void**)&phhi, g_hhi);
    cudaGetSymbolAddress((void**)&phlo, g_hlo);

    cudaFuncSetAttribute(expert_kernel, cudaFuncAttributeMaxDynamicSharedMemorySize, 65536);
    cudaFuncSetAttribute(conv_mma_kernel, cudaFuncAttributeMaxDynamicSharedMemorySize, CONV_SMEM);

    const int WSZ = 196608;
    // ---- pre-convert conv weights to bf16 hi/lo ----
    cvt_hilo_kernel<<<768, 256>>>(rb1_c1w, pwhi,             pwlo,             WSZ);
    cvt_hilo_kernel<<<768, 256>>>(rb1_c2w, pwhi + WSZ,       pwlo + WSZ,       WSZ);
    cvt_hilo_kernel<<<768, 256>>>(rb2_c1w, pwhi + 2*WSZ,     pwlo + 2*WSZ,     WSZ);
    cvt_hilo_kernel<<<768, 256>>>(rb2_c2w, pwhi + 3*WSZ,     pwlo + 3*WSZ,     WSZ);
    cvt_hilo_kernel<<<1536, 256>>>(out_w,  pwhi + 4*WSZ,     pwlo + 4*WSZ,     2*WSZ);

    // ---- res block 1 ----
    gn_gelu_kernel<<<BB * NG, 256>>>(x, emb, rb1_g1s, rb1_g1b, px1, phhi, phlo);
    conv_mma_kernel<<<dim3(32, 4), 256, CONV_SMEM>>>(pwhi, pwlo, phhi, phlo, rb1_c1b, nullptr, pr, 256);
    gn_gelu_kernel<<<BB * NG, 256>>>(pr, nullptr, rb1_g2s, rb1_g2b, nullptr, phhi, phlo);
    conv_mma_kernel<<<dim3(32, 4), 256, CONV_SMEM>>>(pwhi + WSZ, pwlo + WSZ, phhi, phlo, rb1_c2b, px1, pxa, 256);

    // ---- attention (transpose fused into GEMMs) ----
    gemm64<AXT,BROW,CROW><<<dim3(12, 64), 128>>>(pxa, attn_w1, attn_b1, nullptr, pt, 4096, 768, 256);
    qkv_split_kernel<<<4096, 256>>>(pt, pq, pk, pv);
    attn_score_kernel<<<dim3(8, 8, 64), 256>>>(pq, pk, ps);
    softmax512_kernel<<<64 * 512, 128>>>(ps);
    attn_av_kernel<<<dim3(8, 64), 256>>>(ps, pv, poc);
    gemm64<AROW,BROW,CTRANS><<<dim3(4, 64), 128>>>(poc, attn_w2, attn_b2, nullptr, pxb, 4096, 256, 256);

    // ---- res block 2 ----
    gn_gelu_kernel<<<BB * NG, 256>>>(pxb, emb, rb2_g1s, rb2_g1b, px1, phhi, phlo);
    conv_mma_kernel<<<dim3(32, 4), 256, CONV_SMEM>>>(pwhi + 2*WSZ, pwlo + 2*WSZ, phhi, phlo, rb2_c1b, nullptr, pr, 256);
    gn_gelu_kernel<<<BB * NG, 256>>>(pr, nullptr, rb2_g2s, rb2_g2b, nullptr, phhi, phlo);
    conv_mma_kernel<<<dim3(32, 4), 256, CONV_SMEM>>>(pwhi + 3*WSZ, pwlo + 3*WSZ, phhi, phlo, rb2_c2b, px1, pxm, 256);

    // ---- MoE ----
    gemm64<AROW,BROW,CROW><<<dim3(16, 32), 128>>>(pxm, moe_wg, nullptr, nullptr, plog, 2048, 1024, 512);
    gating_kernel<<<2048, 256>>>(plog, praw, pg1, pi1, pg2, pi2);
    rawsum_kernel<<<32, 256>>>(praw, prs);
    routing_kernel<<<BB, 256>>>(pi1, pg1, pi2, pg2, pst, psg, pc1);
    cudaMemsetAsync(pmo, 0, sizeof(float) * BB * CC * LL);
    expert_kernel<<<EE, 256, 65536>>>(pxm, moe_w1, moe_w2, pst, psg, pmo);
    loss_kernel<<<1, 256>>>(prs, pc1, out + 2097152);

    // ---- output conv + maxpool ----
    cvt_hilo_kernel<<<4096, 256>>>(pmo, phhi, phlo, BB * CC * LL);
    conv_mma_kernel<<<dim3(32, 8), 256, CONV_SMEM>>>(pwhi + 4*WSZ, pwlo + 4*WSZ, phhi, phlo, out_b, nullptr, pyf, 512);
    maxpool_kernel<<<4096, 256>>>(pyf, out);

    // second output: moe result x (B,C,L)
    cudaMemcpyAsync(out + 1048576, pmo, sizeof(float) * BB * CC * LL, cudaMemcpyDeviceToDevice);
}

// round 9
// speedup vs baseline: 1.2224x; 1.0472x over previous
#include <cuda_runtime.h>
#include <cuda_bf16.h>
#include <math.h>
#include <stdint.h>

// ---------------- problem constants ----------------
#define BB   8
#define CC   256
#define LL   512
#define NG   32
#define CPG  8
#define NH   8
#define DH   32
#define EE   1024
#define HIDD 32
#define CAPP 4
#define NTOK 256
#define DTOK 512

// ---------------- scratch (device globals; allocation-free) ----------------
__device__ float g_x1[BB*CC*LL];
__device__ float g_r [BB*CC*LL];
__device__ float g_xa[BB*CC*LL];
__device__ float g_t [BB*LL*3*CC];
__device__ float g_q [BB*NH*LL*DH];
__device__ float g_k [BB*NH*LL*DH];
__device__ float g_v [BB*NH*LL*DH];
__device__ float g_s [(size_t)BB*NH*LL*LL];
__device__ float g_oc[BB*LL*CC];
__device__ float g_xb[BB*CC*LL];
__device__ float g_xm[BB*CC*LL];
__device__ float g_logits[BB*NTOK*EE];
__device__ float g_raw  [BB*NTOK*EE];
__device__ float g_gate1[BB*NTOK];
__device__ float g_gate2[BB*NTOK];
__device__ int   g_i1[BB*NTOK];
__device__ int   g_i2[BB*NTOK];
__device__ float g_rawsum[BB*EE];
__device__ float g_cnt1 [BB*EE];
__device__ int   g_slot_tok [BB*EE*CAPP];
__device__ float g_slot_gate[BB*EE*CAPP];
__device__ float g_moeout[BB*CC*LL];
__device__ float g_yfull[(size_t)BB*2*CC*LL];
// bf16 hi/lo operand buffers
#define WSZ 196608
#define OFF_WQKVT (6*WSZ)                  // 256x768 transposed qkv weight
#define OFF_W2T   (OFF_WQKVT + 196608)     // 256x256 transposed proj weight
#define OFF_WGT   (OFF_W2T + 65536)        // 1024x512 transposed gate weight
#define WTOT      (OFF_WGT + 524288)
__device__ unsigned short g_whi[WTOT];
__device__ unsigned short g_wlo[WTOT];
__device__ unsigned short g_hhi[BB*CC*LL];
__device__ unsigned short g_hlo[BB*CC*LL];

__device__ __forceinline__ float gelu_exact(float v) {
    return 0.5f * v * (1.0f + erff(v * 0.7071067811865476f));
}
__device__ __forceinline__ void split_bf16(float v, unsigned short& h, unsigned short& l) {
    __nv_bfloat16 hb = __float2bfloat16(v);
    __nv_bfloat16 lb = __float2bfloat16(v - __bfloat162float(hb));
    h = *(unsigned short*)&hb;
    l = *(unsigned short*)&lb;
}

// ---------------- float -> bf16 hi/lo conversion ----------------
__global__ void cvt_hilo_kernel(const float* __restrict__ src, unsigned short* __restrict__ hi,
                                unsigned short* __restrict__ lo, int n) {
    int i = blockIdx.x * 256 + threadIdx.x;
    if (i < n) {
        unsigned short h, l;
        split_bf16(src[i], h, l);
        hi[i] = h; lo[i] = l;
    }
}

// ---------------- transposed weight cvt: W[K][N] -> Bt[N][K] bf16 hi/lo ----------------
__global__ void cvtT_w_kernel(const float* __restrict__ W, unsigned short* __restrict__ bhi,
                              unsigned short* __restrict__ blo, int K, int N) {
    __shared__ float tile[32][33];
    int k0 = blockIdx.x * 32, n0 = blockIdx.y * 32;
    int x = threadIdx.x, y = threadIdx.y;
#pragma unroll
    for (int i = 0; i < 32; i += 8)
        tile[y + i][x] = W[(size_t)(k0 + y + i) * N + n0 + x];
    __syncthreads();
#pragma unroll
    for (int i = 0; i < 32; i += 8) {
        float v = tile[x][y + i];           // k=k0+x, n=n0+y+i
        unsigned short h, l;
        split_bf16(v, h, l);
        size_t o = (size_t)(n0 + y + i) * K + k0 + x;
        bhi[o] = h; blo[o] = l;
    }
}

// ---------------- transposed activation cvt: xa(B,C,L) -> A[(b*L+l)][C] hi/lo ----------------
__global__ void cvtT_x_kernel(const float* __restrict__ X, unsigned short* __restrict__ ahi,
                              unsigned short* __restrict__ alo) {
    __shared__ float tile[32][33];
    int b = blockIdx.z;
    int l0 = blockIdx.x * 32, c0 = blockIdx.y * 32;
    int x = threadIdx.x, y = threadIdx.y;
#pragma unroll
    for (int i = 0; i < 32; i += 8)
        tile[y + i][x] = X[(((size_t)(b * CC + c0 + y + i)) << 9) + l0 + x];
    __syncthreads();
#pragma unroll
    for (int i = 0; i < 32; i += 8) {
        float v = tile[x][y + i];           // c=c0+x, l=l0+y+i
        unsigned short h, l;
        split_bf16(v, h, l);
        size_t o = (size_t)(b * LL + l0 + y + i) * CC + c0 + x;
        ahi[o] = h; alo[o] = l;
    }
}

// ================= warp-level bf16 MMA (m16n8k16, f32 accum) =================
__device__ __forceinline__ void mma16816(float* c, const uint32_t* a, const uint32_t* b) {
    asm volatile("mma.sync.aligned.m16n8k16.row.col.f32.bf16.bf16.f32 "
        "{%0,%1,%2,%3}, {%4,%5,%6,%7}, {%8,%9}, {%0,%1,%2,%3};"
        : "+f"(c[0]), "+f"(c[1]), "+f"(c[2]), "+f"(c[3])
        : "r"(a[0]), "r"(a[1]), "r"(a[2]), "r"(a[3]), "r"(b[0]), "r"(b[1]));
}

#define CPITCH 72
#define OFF_AHI 0
#define OFF_ALO (64*CPITCH)
#define OFF_BHI (2*64*CPITCH)
#define OFF_BLO (2*64*CPITCH + 128*CPITCH)
#define MMA_SMEM ((2*64*CPITCH + 2*128*CPITCH) * 2)   // 55296 bytes

// ================= tensor-core conv1d(k=3,pad=1) =================
__global__ void __launch_bounds__(256, 2)
conv_mma_kernel(const unsigned short* __restrict__ Whi, const unsigned short* __restrict__ Wlo,
                const unsigned short* __restrict__ Xhi, const unsigned short* __restrict__ Xlo,
                const float* __restrict__ bias, const float* __restrict__ res,
                float* __restrict__ Y, int M) {
    extern __shared__ unsigned short sm[];
    int tid = threadIdx.x;
    int wid = tid >> 5, lane = tid & 31;
    int g = lane >> 2, tg = lane & 3;
    int warp_m = wid & 1, warp_n = wid >> 1;
    int n0 = blockIdx.x * 128, m0 = blockIdx.y * 64;
    int bI = n0 >> 9, l0 = n0 & 511;

    const unsigned short* Wh = Whi + (size_t)m0 * 768;
    const unsigned short* Wl = Wlo + (size_t)m0 * 768;
    const unsigned short* Xh = Xhi + (((size_t)bI * CC) << 9);
    const unsigned short* Xl = Xlo + (((size_t)bI * CC) << 9);

    float acc[2][4][4];
#pragma unroll
    for (int mi = 0; mi < 2; mi++)
#pragma unroll
        for (int ni = 0; ni < 4; ni++)
#pragma unroll
            for (int r = 0; r < 4; r++) acc[mi][ni][r] = 0.f;

    int fa_m = tid >> 2, fa_k = (tid & 3) * 16;
    int fb_n = tid >> 1, fb_h = (tid & 1) * 32;

    for (int c = 0; c < 12; c++) {
        int c64 = c * 64;
        {
            const unsigned short* ph = Wh + (size_t)fa_m * 768 + c64 + fa_k;
            const unsigned short* pl = Wl + (size_t)fa_m * 768 + c64 + fa_k;
            uint4 h0 = *(const uint4*)ph;
            uint4 h1 = *(const uint4*)(ph + 8);
            uint4 l0v = *(const uint4*)pl;
            uint4 l1v = *(const uint4*)(pl + 8);
            *(uint4*)&sm[OFF_AHI + fa_m * CPITCH + fa_k]     = h0;
            *(uint4*)&sm[OFF_AHI + fa_m * CPITCH + fa_k + 8] = h1;
            *(uint4*)&sm[OFF_ALO + fa_m * CPITCH + fa_k]     = l0v;
            *(uint4*)&sm[OFF_ALO + fa_m * CPITCH + fa_k + 8] = l1v;
        }
        {
            int kg = c64 + fb_h;
            int ic = kg / 3, t = kg - 3 * ic;
            int l = l0 + fb_n;
            unsigned short* dh = &sm[OFF_BHI + fb_n * CPITCH + fb_h];
            unsigned short* dl = &sm[OFF_BLO + fb_n * CPITCH + fb_h];
#pragma unroll 8
            for (int i = 0; i < 32; i++) {
                int ll = l + t - 1;
                bool ok = ((unsigned)ll < 512u);
                int src = (ic << 9) + ll;
                dh[i] = ok ? Xh[src] : (unsigned short)0;
                dl[i] = ok ? Xl[src] : (unsigned short)0;
                if (++t == 3) { t = 0; ++ic; }
            }
        }
        __syncthreads();
#pragma unroll
        for (int ks = 0; ks < 4; ks++) {
            int k0 = ks * 16;
            uint32_t ahi[2][4], alo[2][4], bhi[4][2], blo[4][2];
#pragma unroll
            for (int mi = 0; mi < 2; mi++) {
                int r0 = warp_m * 32 + mi * 16 + g;
                const unsigned short* p0 = &sm[OFF_AHI + r0 * CPITCH + k0 + tg * 2];
                const unsigned short* p1 = p0 + 8 * CPITCH;
                ahi[mi][0] = *(const uint32_t*)p0;
                ahi[mi][1] = *(const uint32_t*)p1;
                ahi[mi][2] = *(const uint32_t*)(p0 + 8);
                ahi[mi][3] = *(const uint32_t*)(p1 + 8);
                const unsigned short* q0 = &sm[OFF_ALO + r0 * CPITCH + k0 + tg * 2];
                const unsigned short* q1 = q0 + 8 * CPITCH;
                alo[mi][0] = *(const uint32_t*)q0;
                alo[mi][1] = *(const uint32_t*)q1;
                alo[mi][2] = *(const uint32_t*)(q0 + 8);
                alo[mi][3] = *(const uint32_t*)(q1 + 8);
            }
#pragma unroll
            for (int ni = 0; ni < 4; ni++) {
                int nr = warp_n * 32 + ni * 8 + g;
                const unsigned short* p = &sm[OFF_BHI + nr * CPITCH + k0 + tg * 2];
                bhi[ni][0] = *(const uint32_t*)p;
                bhi[ni][1] = *(const uint32_t*)(p + 8);
                const unsigned short* q = &sm[OFF_BLO + nr * CPITCH + k0 + tg * 2];
                blo[ni][0] = *(const uint32_t*)q;
                blo[ni][1] = *(const uint32_t*)(q + 8);
            }
#pragma unroll
            for (int mi = 0; mi < 2; mi++)
#pragma unroll
                for (int ni = 0; ni < 4; ni++) {
                    mma16816(acc[mi][ni], ahi[mi], bhi[ni]);
                    mma16816(acc[mi][ni], ahi[mi], blo[ni]);
                    mma16816(acc[mi][ni], alo[mi], bhi[ni]);
                }
        }
        __syncthreads();
    }

#pragma unroll
    for (int mi = 0; mi < 2; mi++) {
        int m = m0 + warp_m * 32 + mi * 16 + g;
        float bs0 = bias[m], bs1 = bias[m + 8];
        size_t row0 = (((size_t)bI * M + m) << 9) + l0;
        size_t row1 = (((size_t)bI * M + m + 8) << 9) + l0;
#pragma unroll
        for (int ni = 0; ni < 4; ni++) {
            int ncol = warp_n * 32 + ni * 8 + tg * 2;
            float2 v0 = make_float2(acc[mi][ni][0] + bs0, acc[mi][ni][1] + bs0);
            float2 v1 = make_float2(acc[mi][ni][2] + bs1, acc[mi][ni][3] + bs1);
            if (res) {
                float2 r0 = *(const float2*)&res[row0 + ncol];
                float2 r1 = *(const float2*)&res[row1 + ncol];
                v0.x += r0.x; v0.y += r0.y; v1.x += r1.x; v1.y += r1.y;
            }
            *(float2*)&Y[row0 + ncol] = v0;
            *(float2*)&Y[row1 + ncol] = v1;
        }
    }
}

// ================= generic tensor-core GEMM: C[M,N] = A[M,K] @ Bt[N,K]^T =================
// A, Bt pre-converted to bf16 hi/lo. NT=3: drop lo*lo; NT=4: full split (for logits/argmax).
// CM: 0 = row-major C (+bias[n]); 2 = CTRANS C[((b*N+n)<<9)+l], m=b*512+l (+bias[n]).
template<int CM, int NT>
__global__ void __launch_bounds__(256, 2)
gemm_mma(const unsigned short* __restrict__ Ahi, const unsigned short* __restrict__ Alo,
         const unsigned short* __restrict__ Bthi, const unsigned short* __restrict__ Btlo,
         const float* __restrict__ bias, float* __restrict__ C, int M, int N, int K) {
    extern __shared__ unsigned short sm[];
    int tid = threadIdx.x;
    int wid = tid >> 5, lane = tid & 31;
    int g = lane >> 2, tg = lane & 3;
    int warp_m = wid & 1, warp_n = wid >> 1;
    int n0 = blockIdx.x * 128, m0 = blockIdx.y * 64;

    const unsigned short* Ah = Ahi + (size_t)m0 * K;
    const unsigned short* Al = Alo + (size_t)m0 * K;
    const unsigned short* Bh = Bthi + (size_t)n0 * K;
    const unsigned short* Bl = Btlo + (size_t)n0 * K;

    float acc[2][4][4];
#pragma unroll
    for (int mi = 0; mi < 2; mi++)
#pragma unroll
        for (int ni = 0; ni < 4; ni++)
#pragma unroll
            for (int r = 0; r < 4; r++) acc[mi][ni][r] = 0.f;

    int fa_m = tid >> 2, fa_k = (tid & 3) * 16;
    int fb_n = tid >> 1, fb_h = (tid & 1) * 32;
    int nchunks = K >> 6;

    for (int c = 0; c < nchunks; c++) {
        int c64 = c << 6;
        {
            const unsigned short* ph = Ah + (size_t)fa_m * K + c64 + fa_k;
            const unsigned short* pl = Al + (size_t)fa_m * K + c64 + fa_k;
            *(uint4*)&sm[OFF_AHI + fa_m * CPITCH + fa_k]     = *(const uint4*)ph;
            *(uint4*)&sm[OFF_AHI + fa_m * CPITCH + fa_k + 8] = *(const uint4*)(ph + 8);
            *(uint4*)&sm[OFF_ALO + fa_m * CPITCH + fa_k]     = *(const uint4*)pl;
            *(uint4*)&sm[OFF_ALO + fa_m * CPITCH + fa_k + 8] = *(const uint4*)(pl + 8);
        }
        {
            const unsigned short* ph = Bh + (size_t)fb_n * K + c64 + fb_h;
            const unsigned short* pl = Bl + (size_t)fb_n * K + c64 + fb_h;
            unsigned short* dh = &sm[OFF_BHI + fb_n * CPITCH + fb_h];
            unsigned short* dl = &sm[OFF_BLO + fb_n * CPITCH + fb_h];
#pragma unroll
            for (int i = 0; i < 4; i++) {
                *(uint4*)(dh + i * 8) = *(const uint4*)(ph + i * 8);
                *(uint4*)(dl + i * 8) = *(const uint4*)(pl + i * 8);
            }
        }
        __syncthreads();
#pragma unroll
        for (int ks = 0; ks < 4; ks++) {
            int k0 = ks * 16;
            uint32_t ahi[2][4], alo[2][4], bhi[4][2], blo[4][2];
#pragma unroll
            for (int mi = 0; mi < 2; mi++) {
                int r0 = warp_m * 32 + mi * 16 + g;
                const unsigned short* p0 = &sm[OFF_AHI + r0 * CPITCH + k0 + tg * 2];
                const unsigned short* p1 = p0 + 8 * CPITCH;
                ahi[mi][0] = *(const uint32_t*)p0;
                ahi[mi][1] = *(const uint32_t*)p1;
                ahi[mi][2] = *(const uint32_t*)(p0 + 8);
                ahi[mi][3] = *(const uint32_t*)(p1 + 8);
                const unsigned short* q0 = &sm[OFF_ALO + r0 * CPITCH + k0 + tg * 2];
                const unsigned short* q1 = q0 + 8 * CPITCH;
                alo[mi][0] = *(const uint32_t*)q0;
                alo[mi][1] = *(const uint32_t*)q1;
                alo[mi][2] = *(const uint32_t*)(q0 + 8);
                alo[mi][3] = *(const uint32_t*)(q1 + 8);
            }
#pragma unroll
            for (int ni = 0; ni < 4; ni++) {
                int nr = warp_n * 32 + ni * 8 + g;
                const unsigned short* p = &sm[OFF_BHI + nr * CPITCH + k0 + tg * 2];
                bhi[ni][0] = *(const uint32_t*)p;
                bhi[ni][1] = *(const uint32_t*)(p + 8);
                const unsigned short* q = &sm[OFF_BLO + nr * CPITCH + k0 + tg * 2];
                blo[ni][0] = *(const uint32_t*)q;
                blo[ni][1] = *(const uint32_t*)(q + 8);
            }
#pragma unroll
            for (int mi = 0; mi < 2; mi++)
#pragma unroll
                for (int ni = 0; ni < 4; ni++) {
                    mma16816(acc[mi][ni], ahi[mi], bhi[ni]);
                    mma16816(acc[mi][ni], ahi[mi], blo[ni]);
                    mma16816(acc[mi][ni], alo[mi], bhi[ni]);
                    if (NT == 4) mma16816(acc[mi][ni], alo[mi], blo[ni]);
                }
        }
        __syncthreads();
    }

    if (CM == 0) {
#pragma unroll
        for (int mi = 0; mi < 2; mi++) {
            int m = m0 + warp_m * 32 + mi * 16 + g;
#pragma unroll
            for (int ni = 0; ni < 4; ni++) {
                int n = n0 + warp_n * 32 + ni * 8 + tg * 2;
                float b0 = bias ? bias[n] : 0.f;
                float b1 = bias ? bias[n + 1] : 0.f;
                *(float2*)&C[(size_t)m * N + n] =
                    make_float2(acc[mi][ni][0] + b0, acc[mi][ni][1] + b1);
                *(float2*)&C[(size_t)(m + 8) * N + n] =
                    make_float2(acc[mi][ni][2] + b0, acc[mi][ni][3] + b1);
            }
        }
    } else {
        // CTRANS: m = b*512+l -> C[((b*N + n)<<9) + l]
#pragma unroll
        for (int mi = 0; mi < 2; mi++) {
            int m = m0 + warp_m * 32 + mi * 16 + g;
            int bI = m >> 9, l = m & 511;
#pragma unroll
            for (int ni = 0; ni < 4; ni++) {
                int n = n0 + warp_n * 32 + ni * 8 + tg * 2;
                float b0 = bias ? bias[n] : 0.f;
                float b1 = bias ? bias[n + 1] : 0.f;
                C[(((size_t)(bI * N + n)) << 9) + l]           = acc[mi][ni][0] + b0;
                C[(((size_t)(bI * N + n + 1)) << 9) + l]       = acc[mi][ni][1] + b1;
                C[(((size_t)(bI * N + n)) << 9) + l + 8]       = acc[mi][ni][2] + b0;
                C[(((size_t)(bI * N + n + 1)) << 9) + l + 8]   = acc[mi][ni][3] + b1;
            }
        }
    }
}

// ---------------- GroupNorm (+optional emb add) + GELU, fused; bf16 hi/lo output ----------------
__global__ void gn_gelu_kernel(const float* __restrict__ xin, const float* __restrict__ emb,
                               const float* __restrict__ scale, const float* __restrict__ bias,
                               float* __restrict__ x1_out,
                               unsigned short* __restrict__ hhi, unsigned short* __restrict__ hlo) {
    int b = blockIdx.x >> 5;
    int g = blockIdx.x & 31;
    size_t base = ((size_t)b * CC + g * CPG) * LL;
    __shared__ float vals[CPG * LL];
    __shared__ float red[256];
    int tid = threadIdx.x;
    float s = 0.f, s2 = 0.f;
#pragma unroll
    for (int i = 0; i < 16; i++) {
        int j = tid + i * 256;
        float v = xin[base + j];
        if (emb) v += emb[base + j];
        vals[j] = v;
        s += v;
        s2 = fmaf(v, v, s2);
    }
    red[tid] = s; __syncthreads();
    for (int o = 128; o > 0; o >>= 1) { if (tid < o) red[tid] += red[tid + o]; __syncthreads(); }
    float mean = red[0] * (1.f / 4096.f);
    __syncthreads();
    red[tid] = s2; __syncthreads();
    for (int o = 128; o > 0; o >>= 1) { if (tid < o) red[tid] += red[tid + o]; __syncthreads(); }
    float var = red[0] * (1.f / 4096.f) - mean * mean;
    float rsig = rsqrtf(var + 1e-5f);
#pragma unroll
    for (int i = 0; i < 16; i++) {
        int j = tid + i * 256;
        int c = g * CPG + (j >> 9);
        float v = vals[j];
        if (x1_out) x1_out[base + j] = v;
        float nn = (v - mean) * rsig * scale[c] + bias[c];
        float hv = gelu_exact(nn);
        unsigned short hu, lu;
        split_bf16(hv, hu, lu);
        hhi[base + j] = hu;
        hlo[base + j] = lu;
    }
}

// ---------------- qkv split: t(B,L,768) -> Q,K,V (B,H,L,DH) ----------------
__global__ void qkv_split_kernel(const float* __restrict__ t, float* __restrict__ Q,
                                 float* __restrict__ K, float* __restrict__ V) {
    int idx = blockIdx.x * 256 + threadIdx.x;
    int d = idx & 31;
    int l = (idx >> 5) & 511;
    int h = (idx >> 14) & 7;
    int b = idx >> 17;
    size_t base = ((size_t)(b * LL + l)) * 768 + (size_t)(d * NH + h) * 3;
    int o = ((b * NH + h) * LL + l) * DH + d;
    Q[o] = t[base];
    K[o] = t[base + 1];
    V[o] = t[base + 2];
}

// ---------------- scores S[bh,q,k] = Q.K / sqrt(DH) ----------------
__global__ void attn_score_kernel(const float* __restrict__ Q, const float* __restrict__ K,
                                  float* __restrict__ S) {
    int bh = blockIdx.z;
    int q0 = blockIdx.y * 64, k0 = blockIdx.x * 64;
    __shared__ float Qs[64][33];
    __shared__ float Ks[64][33];
    int tid = threadIdx.x;
#pragma unroll
    for (int i = 0; i < 8; i++) {
        int idx = tid + i * 256;
        int r = idx >> 5, d = idx & 31;
        Qs[r][d] = Q[((size_t)(bh << 9) + q0 + r) * 32 + d];
        Ks[r][d] = K[((size_t)(bh << 9) + k0 + r) * 32 + d];
    }
    __syncthreads();
    int tx = tid & 15, ty = tid >> 4;
    float acc[4][4] = {};
#pragma unroll
    for (int kk = 0; kk < 32; kk++) {
        float a[4], bq[4];
#pragma unroll
        for (int i = 0; i < 4; i++) a[i] = Qs[ty * 4 + i][kk];
#pragma unroll
        for (int j = 0; j < 4; j++) bq[j] = Ks[tx * 4 + j][kk];
#pragma unroll
        for (int i = 0; i < 4; i++)
#pragma unroll
            for (int j = 0; j < 4; j++) acc[i][j] = fmaf(a[i], bq[j], acc[i][j]);
    }
    const float sc = 0.17677669529663687f;
    size_t base = (size_t)bh << 18;
#pragma unroll
    for (int i = 0; i < 4; i++)
#pragma unroll
        for (int j = 0; j < 4; j++)
            S[base + (size_t)(q0 + ty * 4 + i) * 512 + k0 + tx * 4 + j] = acc[i][j] * sc;
}

// ---------------- softmax over rows of 512 ----------------
__global__ void softmax512_kernel(float* __restrict__ S) {
    size_t row = blockIdx.x;
    float* p = S + row * 512;
    int tid = threadIdx.x;       // 128
    __shared__ float red[128];
    float v[4];
#pragma unroll
    for (int i = 0; i < 4; i++) v[i] = p[tid + i * 128];
    float m = fmaxf(fmaxf(v[0], v[1]), fmaxf(v[2], v[3]));
    red[tid] = m; __syncthreads();
    for (int o = 64; o > 0; o >>= 1) { if (tid < o) red[tid] = fmaxf(red[tid], red[tid + o]); __syncthreads(); }
    m = red[0]; __syncthreads();
    float s = 0.f;
#pragma unroll
    for (int i = 0; i < 4; i++) { v[i] = expf(v[i] - m); s += v[i]; }
    red[tid] = s; __syncthreads();
    for (int o = 64; o > 0; o >>= 1) { if (tid < o) red[tid] += red[tid + o]; __syncthreads(); }
    float inv = 1.f / red[0];
#pragma unroll
    for (int i = 0; i < 4; i++) p[tid + i * 128] = v[i] * inv;
}

// ---------------- O = P @ V, write as oc[b,l, d*H + h] ----------------
__global__ void attn_av_kernel(const float* __restrict__ S, const float* __restrict__ V,
                               float* __restrict__ OCb) {
    int bh = blockIdx.y;
    int q0 = blockIdx.x * 64;
    int b = bh >> 3, h = bh & 7;
    __shared__ float Ps[64][65];
    __shared__ float Vs[64][32];
    int tid = threadIdx.x;
    int d = tid & 31, qg = tid >> 5;
    float acc[8] = {};
    for (int k0 = 0; k0 < 512; k0 += 64) {
#pragma unroll
        for (int i = 0; i < 16; i++) {
            int idx = tid + i * 256;
            int r = idx >> 6, c = idx & 63;
            Ps[r][c] = S[((size_t)bh << 18) + (size_t)(q0 + r) * 512 + k0 + c];
        }
#pragma unroll
        for (int i = 0; i < 8; i++) {
            int idx = tid + i * 256;
            int r = idx >> 5, c = idx & 31;
            Vs[r][c] = V[((size_t)(bh << 9) + k0 + r) * 32 + c];
        }
        __syncthreads();
#pragma unroll
        for (int kk = 0; kk < 64; kk++) {
            float vv = Vs[kk][d];
#pragma unroll
            for (int j = 0; j < 8; j++) acc[j] = fmaf(Ps[qg + j * 8][kk], vv, acc[j]);
        }
        __syncthreads();
    }
#pragma unroll
    for (int j = 0; j < 8; j++) {
        int q = q0 + qg + j * 8;
        OCb[((size_t)(b << 9) + q) * 256 + d * NH + h] = acc[j];
    }
}

// ---------------- MoE gating ----------------
__global__ void gating_kernel(const float* __restrict__ logits, float* __restrict__ raw,
                              float* __restrict__ g1, int* __restrict__ i1,
                              float* __restrict__ g2, int* __restrict__ i2) {
    int row = blockIdx.x;
    int tid = threadIdx.x;    // 256
    const float* p = logits + (size_t)row * EE;
    float lv[4];
#pragma unroll
    for (int j = 0; j < 4; j++) lv[j] = p[tid * 4 + j];
    __shared__ float sv[256];
    __shared__ int si[256];
    float bv = lv[0]; int bi = tid * 4;
#pragma unroll
    for (int j = 1; j < 4; j++) if (lv[j] > bv) { bv = lv[j]; bi = tid * 4 + j; }
    sv[tid] = bv; si[tid] = bi; __syncthreads();
    for (int o = 128; o > 0; o >>= 1) {
        if (tid < o) {
            if (sv[tid + o] > sv[tid] || (sv[tid + o] == sv[tid] && si[tid + o] < si[tid])) {
                sv[tid] = sv[tid + o]; si[tid] = si[tid + o];
            }
        }
        __syncthreads();
    }
    float maxv = sv[0]; int maxi = si[0];
    __syncthreads();
    float s = 0.f;
#pragma unroll
    for (int j = 0; j < 4; j++) s += expf(lv[j] - maxv);
    sv[tid] = s; __syncthreads();
    for (int o = 128; o > 0; o >>= 1) { if (tid < o) sv[tid] += sv[tid + o]; __syncthreads(); }
    float inv = 1.f / sv[0];
#pragma unroll
    for (int j = 0; j < 4; j++)
        raw[(size_t)row * EE + tid * 4 + j] = expf(lv[j] - maxv) * inv;
    __syncthreads();
    bv = -3.4e38f; bi = 0;
#pragma unroll
    for (int j = 0; j < 4; j++) {
        int e = tid * 4 + j;
        if (e != maxi && lv[j] > bv) { bv = lv[j]; bi = e; }
    }
    sv[tid] = bv; si[tid] = bi; __syncthreads();
    for (int o = 128; o > 0; o >>= 1) {
        if (tid < o) {
            if (sv[tid + o] > sv[tid] || (sv[tid + o] == sv[tid] && si[tid + o] < si[tid])) {
                sv[tid] = sv[tid + o]; si[tid] = si[tid + o];
            }
        }
        __syncthreads();
    }
    if (tid == 0) {
        float gate1v = inv;
        float gate2v = expf(sv[0] - maxv) * inv;
        float denom = gate1v + gate2v + 1e-9f;
        g1[row] = gate1v / denom;
        i1[row] = maxi;
        g2[row] = gate2v / denom;
        i2[row] = si[0];
    }
}

// ---------------- per-(b,e) sum of raw over tokens ----------------
__global__ void rawsum_kernel(const float* __restrict__ raw, float* __restrict__ rawsum) {
    int b = blockIdx.x >> 2;
    int chunk = blockIdx.x & 3;
    int e = chunk * 256 + threadIdx.x;
    const float* p = raw + (size_t)b * NTOK * EE + e;
    float s = 0.f;
    for (int n = 0; n < NTOK; n++) s += p[(size_t)n * EE];
    rawsum[b * EE + e] = s;
}

// ---------------- routing with capacity ----------------
__global__ void routing_kernel(const int* __restrict__ idx1, const float* __restrict__ gate1,
                               const int* __restrict__ idx2, const float* __restrict__ gate2,
                               int* __restrict__ slot_tok, float* __restrict__ slot_gate,
                               float* __restrict__ cnt1_out) {
    int b = blockIdx.x;
    int tid = threadIdx.x;
    __shared__ int cnt[EE];
    __shared__ int mcnt[EE];
    for (int e = tid; e < EE; e += 256) cnt[e] = 0;
    for (int i = tid; i < EE * CAPP; i += 256) {
        slot_tok[b * EE * CAPP + i] = -1;
        slot_gate[b * EE * CAPP + i] = 0.f;
    }
    __syncthreads();
    if (tid == 0) {
        for (int n = 0; n < NTOK; n++) {
            int e = idx1[b * NTOK + n];
            int pcur = cnt[e]++;
            if (pcur < CAPP) {
                slot_tok[(b * EE + e) * CAPP + pcur] = n;
                slot_gate[(b * EE + e) * CAPP + pcur] = gate1[b * NTOK + n];
            }
        }
    }
    __syncthreads();
    for (int e = tid; e < EE; e += 256) {
        cnt1_out[b * EE + e] = (float)cnt[e];
        mcnt[e] = cnt[e] < CAPP ? cnt[e] : CAPP;
        cnt[e] = 0;
    }
    __syncthreads();
    if (tid == 0) {
        for (int n = 0; n < NTOK; n++) {
            int e = idx2[b * NTOK + n];
            int pcur = mcnt[e] + cnt[e];
            cnt[e]++;
            if (pcur < CAPP) {
                slot_tok[(b * EE + e) * CAPP + pcur] = n;
                slot_gate[(b * EE + e) * CAPP + pcur] = gate2[b * NTOK + n];
            }
        }
    }
}

// ---------------- expert FFN ----------------
__global__ void expert_kernel(const float* __restrict__ xm, const float* __restrict__ w1,
                              const float* __restrict__ w2,
                              const int* __restrict__ slot_tok, const float* __restrict__ slot_gate,
                              float* __restrict__ out) {
    int e = blockIdx.x;
    int tid = threadIdx.x;    // 256
    extern __shared__ float sw[];          // 64 KB
    __shared__ float hsh[32][33];
    __shared__ int stok[32];
    __shared__ float sgate[32];
    __shared__ int s_any;
    if (tid < 32) {
        int b = tid >> 2, c = tid & 3;
        stok[tid]  = slot_tok [(b * EE + e) * CAPP + c];
        sgate[tid] = slot_gate[(b * EE + e) * CAPP + c];
    }
    if (tid == 0) s_any = 0;
    __syncthreads();
    if (tid == 0) {
        int a = 0;
        for (int i = 0; i < 32; i++) a |= (stok[i] >= 0);
        s_any = a;
    }
    __syncthreads();
    if (!s_any) return;
    const float* w1e = w1 + (size_t)e * DTOK * HIDD;
#pragma unroll
    for (int i = 0; i < 64; i++) sw[tid + i * 256] = w1e[tid + i * 256];
    __syncthreads();
    int hid = tid & 31;
#pragma unroll
    for (int pass = 0; pass < 4; pass++) {
        int sidx = pass * 8 + (tid >> 5);
        int tok = stok[sidx];
        float acc = 0.f;
        if (tok >= 0) {
            const float* xr = xm + ((size_t)((sidx >> 2) * NTOK + tok)) * DTOK;
            for (int dd = 0; dd < DTOK; dd++) acc = fmaf(xr[dd], sw[dd * HIDD + hid], acc);
        }
        hsh[sidx][hid] = gelu_exact(acc);
    }
    __syncthreads();
    const float* w2e = w2 + (size_t)e * HIDD * DTOK;
#pragma unroll
    for (int i = 0; i < 64; i++) sw[tid + i * 256] = w2e[tid + i * 256];
    __syncthreads();
#pragma unroll
    for (int i = 0; i < 64; i++) {
        int idx = tid + i * 256;
        int sidx = idx >> 9;
        int dd = idx & 511;
        int tok = stok[sidx];
        float g = sgate[sidx];
        if (tok >= 0 && g != 0.f) {
            float acc = 0.f;
#pragma unroll
            for (int h2 = 0; h2 < HIDD; h2++) acc = fmaf(hsh[sidx][h2], sw[h2 * DTOK + dd], acc);
            atomicAdd(&out[((size_t)((sidx >> 2) * NTOK + tok)) * DTOK + dd], g * acc);
        }
    }
}

// ---------------- aux loss ----------------
__global__ void loss_kernel(const float* __restrict__ rawsum, const float* __restrict__ cnt1,
                            float* __restrict__ out_scalar) {
    __shared__ float red[256];
    int tid = threadIdx.x;
    float s = 0.f;
    for (int i = tid; i < BB * EE; i += 256) s += rawsum[i] * cnt1[i];
    red[tid] = s; __syncthreads();
    for (int o = 128; o > 0; o >>= 1) { if (tid < o) red[tid] += red[tid + o]; __syncthreads(); }
    if (tid == 0) out_scalar[0] = red[0] * 1.953125e-05f;
}

// ---------------- maxpool k=3 s=2 pad=1 ----------------
__global__ void maxpool_kernel(const float* __restrict__ yf, float* __restrict__ out) {
    int idx = blockIdx.x * 256 + threadIdx.x;
    int j = idx & 255;
    int o = (idx >> 8) & 511;
    int b = idx >> 17;
    const float* row = yf + ((size_t)(b * 512 + o)) * 512;
    int l = 2 * j;
    float m = row[l];
    if (l > 0) m = fmaxf(m, row[l - 1]);
    m = fmaxf(m, row[l + 1]);
    out[idx] = m;
}

// ---------------- host orchestration ----------------
extern "C" void kernel_launch(void* const* d_in, const int* in_sizes, int n_in,
                              void* d_out, int out_size) {
    const float* x        = (const float*)d_in[0];
    const float* emb      = (const float*)d_in[1];
    const float* rb1_g1s  = (const float*)d_in[2];
    const float* rb1_g1b  = (const float*)d_in[3];
    const float* rb1_c1w  = (const float*)d_in[4];
    const float* rb1_c1b  = (const float*)d_in[5];
    const float* rb1_g2s  = (const float*)d_in[6];
    const float* rb1_g2b  = (const float*)d_in[7];
    const float* rb1_c2w  = (const float*)d_in[8];
    const float* rb1_c2b  = (const float*)d_in[9];
    const float* rb2_g1s  = (const float*)d_in[10];
    const float* rb2_g1b  = (const float*)d_in[11];
    const float* rb2_c1w  = (const float*)d_in[12];
    const float* rb2_c1b  = (const float*)d_in[13];
    const float* rb2_g2s  = (const float*)d_in[14];
    const float* rb2_g2b  = (const float*)d_in[15];
    const float* rb2_c2w  = (const float*)d_in[16];
    const float* rb2_c2b  = (const float*)d_in[17];
    const float* attn_w1  = (const float*)d_in[18];
    const float* attn_b1  = (const float*)d_in[19];
    const float* attn_w2  = (const float*)d_in[20];
    const float* attn_b2  = (const float*)d_in[21];
    const float* moe_wg   = (const float*)d_in[22];
    const float* moe_w1   = (const float*)d_in[23];
    const float* moe_w2   = (const float*)d_in[24];
    const float* out_w    = (const float*)d_in[25];
    const float* out_b    = (const float*)d_in[26];
    float* out = (float*)d_out;

    float *px1, *pr, *pxa, *pt, *pq, *pk, *pv, *ps, *poc, *pxb, *pxm;
    float *plog, *praw, *pg1, *pg2, *prs, *pc1, *psg, *pmo, *pyf;
    int *pi1, *pi2, *pst;
    unsigned short *pwhi, *pwlo, *phhi, *phlo;
    cudaGetSymbolAddress((void**)&px1, g_x1);
    cudaGetSymbolAddress((void**)&pr,  g_r);
    cudaGetSymbolAddress((void**)&pxa, g_xa);
    cudaGetSymbolAddress((void**)&pt,  g_t);
    cudaGetSymbolAddress((void**)&pq,  g_q);
    cudaGetSymbolAddress((void**)&pk,  g_k);
    cudaGetSymbolAddress((void**)&pv,  g_v);
    cudaGetSymbolAddress((void**)&ps,  g_s);
    cudaGetSymbolAddress((void**)&poc, g_oc);
    cudaGetSymbolAddress((void**)&pxb, g_xb);
    cudaGetSymbolAddress((void**)&pxm, g_xm);
    cudaGetSymbolAddress((void**)&plog, g_logits);
    cudaGetSymbolAddress((void**)&praw, g_raw);
    cudaGetSymbolAddress((void**)&pg1, g_gate1);
    cudaGetSymbolAddress((void**)&pg2, g_gate2);
    cudaGetSymbolAddress((void**)&pi1, g_i1);
    cudaGetSymbolAddress((void**)&pi2, g_i2);
    cudaGetSymbolAddress((void**)&prs, g_rawsum);
    cudaGetSymbolAddress((void**)&pc1, g_cnt1);
    cudaGetSymbolAddress((void**)&pst, g_slot_tok);
    cudaGetSymbolAddress((void**)&psg, g_slot_gate);
    cudaGetSymbolAddress((void**)&pmo, g_moeout);
    cudaGetSymbolAddress((void**)&pyf, g_yfull);
    cudaGetSymbolAddress((void**)&pwhi, g_whi);
    cudaGetSymbolAddress((void**)&pwlo, g_wlo);
    cudaGetSymbolAddress((void**)&phhi, g_hhi);
    cudaGetSymbolAddress((void**)&phlo, g_hlo);

    cudaFuncSetAttribute(expert_kernel, cudaFuncAttributeMaxDynamicSharedMemorySize, 65536);
    cudaFuncSetAttribute(conv_mma_kernel, cudaFuncAttributeMaxDynamicSharedMemorySize, MMA_SMEM);
    cudaFuncSetAttribute(gemm_mma<0,3>, cudaFuncAttributeMaxDynamicSharedMemorySize, MMA_SMEM);
    cudaFuncSetAttribute(gemm_mma<2,3>, cudaFuncAttributeMaxDynamicSharedMemorySize, MMA_SMEM);
    cudaFuncSetAttribute(gemm_mma<0,4>, cudaFuncAttributeMaxDynamicSharedMemorySize, MMA_SMEM);

    // ---- pre-convert conv weights (row-major) and GEMM weights (transposed) ----
    cvt_hilo_kernel<<<768, 256>>>(rb1_c1w, pwhi,         pwlo,         WSZ);
    cvt_hilo_kernel<<<768, 256>>>(rb1_c2w, pwhi + WSZ,   pwlo + WSZ,   WSZ);
    cvt_hilo_kernel<<<768, 256>>>(rb2_c1w, pwhi + 2*WSZ, pwlo + 2*WSZ, WSZ);
    cvt_hilo_kernel<<<768, 256>>>(rb2_c2w, pwhi + 3*WSZ, pwlo + 3*WSZ, WSZ);
    cvt_hilo_kernel<<<1536, 256>>>(out_w,  pwhi + 4*WSZ, pwlo + 4*WSZ, 2*WSZ);
    cvtT_w_kernel<<<dim3(8, 24), dim3(32, 8)>>>(attn_w1, pwhi + OFF_WQKVT, pwlo + OFF_WQKVT, 256, 768);
    cvtT_w_kernel<<<dim3(8, 8),  dim3(32, 8)>>>(attn_w2, pwhi + OFF_W2T,   pwlo + OFF_W2T,   256, 256);
    cvtT_w_kernel<<<dim3(16, 32), dim3(32, 8)>>>(moe_wg, pwhi + OFF_WGT,   pwlo + OFF_WGT,   512, 1024);

    // ---- res block 1 ----
    gn_gelu_kernel<<<BB * NG, 256>>>(x, emb, rb1_g1s, rb1_g1b, px1, phhi, phlo);
    conv_mma_kernel<<<dim3(32, 4), 256, MMA_SMEM>>>(pwhi, pwlo, phhi, phlo, rb1_c1b, nullptr, pr, 256);
    gn_gelu_kernel<<<BB * NG, 256>>>(pr, nullptr, rb1_g2s, rb1_g2b, nullptr, phhi, phlo);
    conv_mma_kernel<<<dim3(32, 4), 256, MMA_SMEM>>>(pwhi + WSZ, pwlo + WSZ, phhi, phlo, rb1_c2b, px1, pxa, 256);

    // ---- attention ----
    cvtT_x_kernel<<<dim3(16, 8, 8), dim3(32, 8)>>>(pxa, phhi, phlo);          // A = xa^T hi/lo
    gemm_mma<0,3><<<dim3(6, 64), 256, MMA_SMEM>>>(phhi, phlo, pwhi + OFF_WQKVT, pwlo + OFF_WQKVT,
                                                  attn_b1, pt, 4096, 768, 256);
    qkv_split_kernel<<<4096, 256>>>(pt, pq, pk, pv);
    attn_score_kernel<<<dim3(8, 8, 64), 256>>>(pq, pk, ps);
    softmax512_kernel<<<64 * 512, 128>>>(ps);
    attn_av_kernel<<<dim3(8, 64), 256>>>(ps, pv, poc);
    cvt_hilo_kernel<<<4096, 256>>>(poc, phhi, phlo, BB * LL * CC);            // A = oc hi/lo
    gemm_mma<2,3><<<dim3(2, 64), 256, MMA_SMEM>>>(phhi, phlo, pwhi + OFF_W2T, pwlo + OFF_W2T,
                                                  attn_b2, pxb, 4096, 256, 256);

    // ---- res block 2 ----
    gn_gelu_kernel<<<BB * NG, 256>>>(pxb, emb, rb2_g1s, rb2_g1b, px1, phhi, phlo);
    conv_mma_kernel<<<dim3(32, 4), 256, MMA_SMEM>>>(pwhi + 2*WSZ, pwlo + 2*WSZ, phhi, phlo, rb2_c1b, nullptr, pr, 256);
    gn_gelu_kernel<<<BB * NG, 256>>>(pr, nullptr, rb2_g2s, rb2_g2b, nullptr, phhi, phlo);
    conv_mma_kernel<<<dim3(32, 4), 256, MMA_SMEM>>>(pwhi + 3*WSZ, pwlo + 3*WSZ, phhi, phlo, rb2_c2b, px1, pxm, 256);

    // ---- MoE ----
    cvt_hilo_kernel<<<4096, 256>>>(pxm, phhi, phlo, BB * CC * LL);            // A = xm hi/lo (2048x512)
    gemm_mma<0,4><<<dim3(8, 32), 256, MMA_SMEM>>>(phhi, phlo, pwhi + OFF_WGT, pwlo + OFF_WGT,
                                                  nullptr, plog, 2048, 1024, 512);
    gating_kernel<<<2048, 256>>>(plog, praw, pg1, pi1, pg2, pi2);
    rawsum_kernel<<<32, 256>>>(praw, prs);
    routing_kernel<<<BB, 256>>>(pi1, pg1, pi2, pg2, pst, psg, pc1);
    cudaMemsetAsync(pmo, 0, sizeof(float) * BB * CC * LL);
    expert_kernel<<<EE, 256, 65536>>>(pxm, moe_w1, moe_w2, pst, psg, pmo);
    loss_kernel<<<1, 256>>>(prs, pc1, out + 2097152);

    // ---- output conv + maxpool ----
    cvt_hilo_kernel<<<4096, 256>>>(pmo, phhi, phlo, BB * CC * LL);
    conv_mma_kernel<<<dim3(32, 8), 256, MMA_SMEM>>>(pwhi + 4*WSZ, pwlo + 4*WSZ, phhi, phlo, out_b, nullptr, pyf, 512);
    maxpool_kernel<<<4096, 256>>>(pyf, out);

    // second output: moe result x (B,C,L)
    cudaMemcpyAsync(out + 1048576, pmo, sizeof(float) * BB * CC * LL, cudaMemcpyDeviceToDevice);
}

// round 10
// speedup vs baseline: 1.2535x; 1.0254x over previous
#include <cuda_runtime.h>
#include <cuda_bf16.h>
#include <math.h>
#include <stdint.h>

// ---------------- problem constants ----------------
#define BB   8
#define CC   256
#define LL   512
#define NG   32
#define CPG  8
#define NH   8
#define DH   32
#define EE   1024
#define HIDD 32
#define CAPP 4
#define NTOK 256
#define DTOK 512

// ---------------- scratch (device globals; allocation-free) ----------------
__device__ float g_x1[BB*CC*LL];
__device__ float g_r [BB*CC*LL];
__device__ float g_xa[BB*CC*LL];
__device__ float g_t [BB*LL*3*CC];
__device__ float g_q [BB*NH*LL*DH];
__device__ float g_k [BB*NH*LL*DH];
__device__ float g_v [BB*NH*LL*DH];
__device__ float g_oc[BB*LL*CC];
__device__ float g_xb[BB*CC*LL];
__device__ float g_xm[BB*CC*LL];
__device__ float g_logits[BB*NTOK*EE];
__device__ float g_raw  [BB*NTOK*EE];
__device__ float g_gate1[BB*NTOK];
__device__ float g_gate2[BB*NTOK];
__device__ int   g_i1[BB*NTOK];
__device__ int   g_i2[BB*NTOK];
__device__ float g_rawsum[BB*EE];
__device__ float g_cnt1 [BB*EE];
__device__ int   g_slot_tok [BB*EE*CAPP];
__device__ float g_slot_gate[BB*EE*CAPP];
__device__ float g_moeout[BB*CC*LL];
__device__ float g_yfull[(size_t)BB*2*CC*LL];
// bf16 hi/lo operand buffers
#define WSZ 196608
#define OFF_WQKVT (6*WSZ)                  // 256x768 transposed qkv weight
#define OFF_W2T   (OFF_WQKVT + 196608)     // 256x256 transposed proj weight
#define OFF_WGT   (OFF_W2T + 65536)        // 1024x512 transposed gate weight
#define WTOT      (OFF_WGT + 524288)
__device__ unsigned short g_whi[WTOT];
__device__ unsigned short g_wlo[WTOT];
__device__ unsigned short g_hhi[BB*CC*LL];
__device__ unsigned short g_hlo[BB*CC*LL];

__device__ __forceinline__ float gelu_exact(float v) {
    return 0.5f * v * (1.0f + erff(v * 0.7071067811865476f));
}
__device__ __forceinline__ void split_bf16(float v, unsigned short& h, unsigned short& l) {
    __nv_bfloat16 hb = __float2bfloat16(v);
    __nv_bfloat16 lb = __float2bfloat16(v - __bfloat162float(hb));
    h = *(unsigned short*)&hb;
    l = *(unsigned short*)&lb;
}

// ---------------- float -> bf16 hi/lo conversion ----------------
__global__ void cvt_hilo_kernel(const float* __restrict__ src, unsigned short* __restrict__ hi,
                                unsigned short* __restrict__ lo, int n) {
    int i = blockIdx.x * 256 + threadIdx.x;
    if (i < n) {
        unsigned short h, l;
        split_bf16(src[i], h, l);
        hi[i] = h; lo[i] = l;
    }
}

// ---------------- transposed weight cvt: W[K][N] -> Bt[N][K] bf16 hi/lo ----------------
__global__ void cvtT_w_kernel(const float* __restrict__ W, unsigned short* __restrict__ bhi,
                              unsigned short* __restrict__ blo, int K, int N) {
    __shared__ float tile[32][33];
    int k0 = blockIdx.x * 32, n0 = blockIdx.y * 32;
    int x = threadIdx.x, y = threadIdx.y;
#pragma unroll
    for (int i = 0; i < 32; i += 8)
        tile[y + i][x] = W[(size_t)(k0 + y + i) * N + n0 + x];
    __syncthreads();
#pragma unroll
    for (int i = 0; i < 32; i += 8) {
        float v = tile[x][y + i];
        unsigned short h, l;
        split_bf16(v, h, l);
        size_t o = (size_t)(n0 + y + i) * K + k0 + x;
        bhi[o] = h; blo[o] = l;
    }
}

// ---------------- transposed activation cvt: xa(B,C,L) -> A[(b*L+l)][C] hi/lo ----------------
__global__ void cvtT_x_kernel(const float* __restrict__ X, unsigned short* __restrict__ ahi,
                              unsigned short* __restrict__ alo) {
    __shared__ float tile[32][33];
    int b = blockIdx.z;
    int l0 = blockIdx.x * 32, c0 = blockIdx.y * 32;
    int x = threadIdx.x, y = threadIdx.y;
#pragma unroll
    for (int i = 0; i < 32; i += 8)
        tile[y + i][x] = X[(((size_t)(b * CC + c0 + y + i)) << 9) + l0 + x];
    __syncthreads();
#pragma unroll
    for (int i = 0; i < 32; i += 8) {
        float v = tile[x][y + i];
        unsigned short h, l;
        split_bf16(v, h, l);
        size_t o = (size_t)(b * LL + l0 + y + i) * CC + c0 + x;
        ahi[o] = h; alo[o] = l;
    }
}

// ================= warp-level bf16 MMA (m16n8k16, f32 accum) =================
__device__ __forceinline__ void mma16816(float* c, const uint32_t* a, const uint32_t* b) {
    asm volatile("mma.sync.aligned.m16n8k16.row.col.f32.bf16.bf16.f32 "
        "{%0,%1,%2,%3}, {%4,%5,%6,%7}, {%8,%9}, {%0,%1,%2,%3};"
        : "+f"(c[0]), "+f"(c[1]), "+f"(c[2]), "+f"(c[3])
        : "r"(a[0]), "r"(a[1]), "r"(a[2]), "r"(a[3]), "r"(b[0]), "r"(b[1]));
}

#define CPITCH 72
#define OFF_AHI 0
#define OFF_ALO (64*CPITCH)
#define OFF_BHI (2*64*CPITCH)
#define OFF_BLO (2*64*CPITCH + 128*CPITCH)
#define MMA_SMEM ((2*64*CPITCH + 2*128*CPITCH) * 2)   // 55296 bytes

// ================= tensor-core conv1d(k=3,pad=1) =================
__global__ void __launch_bounds__(256, 2)
conv_mma_kernel(const unsigned short* __restrict__ Whi, const unsigned short* __restrict__ Wlo,
                const unsigned short* __restrict__ Xhi, const unsigned short* __restrict__ Xlo,
                const float* __restrict__ bias, const float* __restrict__ res,
                float* __restrict__ Y, int M) {
    extern __shared__ unsigned short sm[];
    int tid = threadIdx.x;
    int wid = tid >> 5, lane = tid & 31;
    int g = lane >> 2, tg = lane & 3;
    int warp_m = wid & 1, warp_n = wid >> 1;
    int n0 = blockIdx.x * 128, m0 = blockIdx.y * 64;
    int bI = n0 >> 9, l0 = n0 & 511;

    const unsigned short* Wh = Whi + (size_t)m0 * 768;
    const unsigned short* Wl = Wlo + (size_t)m0 * 768;
    const unsigned short* Xh = Xhi + (((size_t)bI * CC) << 9);
    const unsigned short* Xl = Xlo + (((size_t)bI * CC) << 9);

    float acc[2][4][4];
#pragma unroll
    for (int mi = 0; mi < 2; mi++)
#pragma unroll
        for (int ni = 0; ni < 4; ni++)
#pragma unroll
            for (int r = 0; r < 4; r++) acc[mi][ni][r] = 0.f;

    int fa_m = tid >> 2, fa_k = (tid & 3) * 16;
    int fb_n = tid >> 1, fb_h = (tid & 1) * 32;

    for (int c = 0; c < 12; c++) {
        int c64 = c * 64;
        {
            const unsigned short* ph = Wh + (size_t)fa_m * 768 + c64 + fa_k;
            const unsigned short* pl = Wl + (size_t)fa_m * 768 + c64 + fa_k;
            *(uint4*)&sm[OFF_AHI + fa_m * CPITCH + fa_k]     = *(const uint4*)ph;
            *(uint4*)&sm[OFF_AHI + fa_m * CPITCH + fa_k + 8] = *(const uint4*)(ph + 8);
            *(uint4*)&sm[OFF_ALO + fa_m * CPITCH + fa_k]     = *(const uint4*)pl;
            *(uint4*)&sm[OFF_ALO + fa_m * CPITCH + fa_k + 8] = *(const uint4*)(pl + 8);
        }
        {
            int kg = c64 + fb_h;
            int ic = kg / 3, t = kg - 3 * ic;
            int l = l0 + fb_n;
            unsigned short* dh = &sm[OFF_BHI + fb_n * CPITCH + fb_h];
            unsigned short* dl = &sm[OFF_BLO + fb_n * CPITCH + fb_h];
#pragma unroll 8
            for (int i = 0; i < 32; i++) {
                int ll = l + t - 1;
                bool ok = ((unsigned)ll < 512u);
                int src = (ic << 9) + ll;
                dh[i] = ok ? Xh[src] : (unsigned short)0;
                dl[i] = ok ? Xl[src] : (unsigned short)0;
                if (++t == 3) { t = 0; ++ic; }
            }
        }
        __syncthreads();
#pragma unroll
        for (int ks = 0; ks < 4; ks++) {
            int k0 = ks * 16;
            uint32_t ahi[2][4], alo[2][4], bhi[4][2], blo[4][2];
#pragma unroll
            for (int mi = 0; mi < 2; mi++) {
                int r0 = warp_m * 32 + mi * 16 + g;
                const unsigned short* p0 = &sm[OFF_AHI + r0 * CPITCH + k0 + tg * 2];
                const unsigned short* p1 = p0 + 8 * CPITCH;
                ahi[mi][0] = *(const uint32_t*)p0;
                ahi[mi][1] = *(const uint32_t*)p1;
                ahi[mi][2] = *(const uint32_t*)(p0 + 8);
                ahi[mi][3] = *(const uint32_t*)(p1 + 8);
                const unsigned short* q0 = &sm[OFF_ALO + r0 * CPITCH + k0 + tg * 2];
                const unsigned short* q1 = q0 + 8 * CPITCH;
                alo[mi][0] = *(const uint32_t*)q0;
                alo[mi][1] = *(const uint32_t*)q1;
                alo[mi][2] = *(const uint32_t*)(q0 + 8);
                alo[mi][3] = *(const uint32_t*)(q1 + 8);
            }
#pragma unroll
            for (int ni = 0; ni < 4; ni++) {
                int nr = warp_n * 32 + ni * 8 + g;
                const unsigned short* p = &sm[OFF_BHI + nr * CPITCH + k0 + tg * 2];
                bhi[ni][0] = *(const uint32_t*)p;
                bhi[ni][1] = *(const uint32_t*)(p + 8);
                const unsigned short* q = &sm[OFF_BLO + nr * CPITCH + k0 + tg * 2];
                blo[ni][0] = *(const uint32_t*)q;
                blo[ni][1] = *(const uint32_t*)(q + 8);
            }
#pragma unroll
            for (int mi = 0; mi < 2; mi++)
#pragma unroll
                for (int ni = 0; ni < 4; ni++) {
                    mma16816(acc[mi][ni], ahi[mi], bhi[ni]);
                    mma16816(acc[mi][ni], ahi[mi], blo[ni]);
                    mma16816(acc[mi][ni], alo[mi], bhi[ni]);
                }
        }
        __syncthreads();
    }

#pragma unroll
    for (int mi = 0; mi < 2; mi++) {
        int m = m0 + warp_m * 32 + mi * 16 + g;
        float bs0 = bias[m], bs1 = bias[m + 8];
        size_t row0 = (((size_t)bI * M + m) << 9) + l0;
        size_t row1 = (((size_t)bI * M + m + 8) << 9) + l0;
#pragma unroll
        for (int ni = 0; ni < 4; ni++) {
            int ncol = warp_n * 32 + ni * 8 + tg * 2;
            float2 v0 = make_float2(acc[mi][ni][0] + bs0, acc[mi][ni][1] + bs0);
            float2 v1 = make_float2(acc[mi][ni][2] + bs1, acc[mi][ni][3] + bs1);
            if (res) {
                float2 r0 = *(const float2*)&res[row0 + ncol];
                float2 r1 = *(const float2*)&res[row1 + ncol];
                v0.x += r0.x; v0.y += r0.y; v1.x += r1.x; v1.y += r1.y;
            }
            *(float2*)&Y[row0 + ncol] = v0;
            *(float2*)&Y[row1 + ncol] = v1;
        }
    }
}

// ================= generic tensor-core GEMM: C[M,N] = A[M,K] @ Bt[N,K]^T =================
template<int CM, int NT>
__global__ void __launch_bounds__(256, 2)
gemm_mma(const unsigned short* __restrict__ Ahi, const unsigned short* __restrict__ Alo,
         const unsigned short* __restrict__ Bthi, const unsigned short* __restrict__ Btlo,
         const float* __restrict__ bias, float* __restrict__ C, int M, int N, int K) {
    extern __shared__ unsigned short sm[];
    int tid = threadIdx.x;
    int wid = tid >> 5, lane = tid & 31;
    int g = lane >> 2, tg = lane & 3;
    int warp_m = wid & 1, warp_n = wid >> 1;
    int n0 = blockIdx.x * 128, m0 = blockIdx.y * 64;

    const unsigned short* Ah = Ahi + (size_t)m0 * K;
    const unsigned short* Al = Alo + (size_t)m0 * K;
    const unsigned short* Bh = Bthi + (size_t)n0 * K;
    const unsigned short* Bl = Btlo + (size_t)n0 * K;

    float acc[2][4][4];
#pragma unroll
    for (int mi = 0; mi < 2; mi++)
#pragma unroll
        for (int ni = 0; ni < 4; ni++)
#pragma unroll
            for (int r = 0; r < 4; r++) acc[mi][ni][r] = 0.f;

    int fa_m = tid >> 2, fa_k = (tid & 3) * 16;
    int fb_n = tid >> 1, fb_h = (tid & 1) * 32;
    int nchunks = K >> 6;

    for (int c = 0; c < nchunks; c++) {
        int c64 = c << 6;
        {
            const unsigned short* ph = Ah + (size_t)fa_m * K + c64 + fa_k;
            const unsigned short* pl = Al + (size_t)fa_m * K + c64 + fa_k;
            *(uint4*)&sm[OFF_AHI + fa_m * CPITCH + fa_k]     = *(const uint4*)ph;
            *(uint4*)&sm[OFF_AHI + fa_m * CPITCH + fa_k + 8] = *(const uint4*)(ph + 8);
            *(uint4*)&sm[OFF_ALO + fa_m * CPITCH + fa_k]     = *(const uint4*)pl;
            *(uint4*)&sm[OFF_ALO + fa_m * CPITCH + fa_k + 8] = *(const uint4*)(pl + 8);
        }
        {
            const unsigned short* ph = Bh + (size_t)fb_n * K + c64 + fb_h;
            const unsigned short* pl = Bl + (size_t)fb_n * K + c64 + fb_h;
            unsigned short* dh = &sm[OFF_BHI + fb_n * CPITCH + fb_h];
            unsigned short* dl = &sm[OFF_BLO + fb_n * CPITCH + fb_h];
#pragma unroll
            for (int i = 0; i < 4; i++) {
                *(uint4*)(dh + i * 8) = *(const uint4*)(ph + i * 8);
                *(uint4*)(dl + i * 8) = *(const uint4*)(pl + i * 8);
            }
        }
        __syncthreads();
#pragma unroll
        for (int ks = 0; ks < 4; ks++) {
            int k0 = ks * 16;
            uint32_t ahi[2][4], alo[2][4], bhi[4][2], blo[4][2];
#pragma unroll
            for (int mi = 0; mi < 2; mi++) {
                int r0 = warp_m * 32 + mi * 16 + g;
                const unsigned short* p0 = &sm[OFF_AHI + r0 * CPITCH + k0 + tg * 2];
                const unsigned short* p1 = p0 + 8 * CPITCH;
                ahi[mi][0] = *(const uint32_t*)p0;
                ahi[mi][1] = *(const uint32_t*)p1;
                ahi[mi][2] = *(const uint32_t*)(p0 + 8);
                ahi[mi][3] = *(const uint32_t*)(p1 + 8);
                const unsigned short* q0 = &sm[OFF_ALO + r0 * CPITCH + k0 + tg * 2];
                const unsigned short* q1 = q0 + 8 * CPITCH;
                alo[mi][0] = *(const uint32_t*)q0;
                alo[mi][1] = *(const uint32_t*)q1;
                alo[mi][2] = *(const uint32_t*)(q0 + 8);
                alo[mi][3] = *(const uint32_t*)(q1 + 8);
            }
#pragma unroll
            for (int ni = 0; ni < 4; ni++) {
                int nr = warp_n * 32 + ni * 8 + g;
                const unsigned short* p = &sm[OFF_BHI + nr * CPITCH + k0 + tg * 2];
                bhi[ni][0] = *(const uint32_t*)p;
                bhi[ni][1] = *(const uint32_t*)(p + 8);
                const unsigned short* q = &sm[OFF_BLO + nr * CPITCH + k0 + tg * 2];
                blo[ni][0] = *(const uint32_t*)q;
                blo[ni][1] = *(const uint32_t*)(q + 8);
            }
#pragma unroll
            for (int mi = 0; mi < 2; mi++)
#pragma unroll
                for (int ni = 0; ni < 4; ni++) {
                    mma16816(acc[mi][ni], ahi[mi], bhi[ni]);
                    mma16816(acc[mi][ni], ahi[mi], blo[ni]);
                    mma16816(acc[mi][ni], alo[mi], bhi[ni]);
                    if (NT == 4) mma16816(acc[mi][ni], alo[mi], blo[ni]);
                }
        }
        __syncthreads();
    }

    if (CM == 0) {
#pragma unroll
        for (int mi = 0; mi < 2; mi++) {
            int m = m0 + warp_m * 32 + mi * 16 + g;
#pragma unroll
            for (int ni = 0; ni < 4; ni++) {
                int n = n0 + warp_n * 32 + ni * 8 + tg * 2;
                float b0 = bias ? bias[n] : 0.f;
                float b1 = bias ? bias[n + 1] : 0.f;
                *(float2*)&C[(size_t)m * N + n] =
                    make_float2(acc[mi][ni][0] + b0, acc[mi][ni][1] + b1);
                *(float2*)&C[(size_t)(m + 8) * N + n] =
                    make_float2(acc[mi][ni][2] + b0, acc[mi][ni][3] + b1);
            }
        }
    } else {
#pragma unroll
        for (int mi = 0; mi < 2; mi++) {
            int m = m0 + warp_m * 32 + mi * 16 + g;
            int bI = m >> 9, l = m & 511;
#pragma unroll
            for (int ni = 0; ni < 4; ni++) {
                int n = n0 + warp_n * 32 + ni * 8 + tg * 2;
                float b0 = bias ? bias[n] : 0.f;
                float b1 = bias ? bias[n + 1] : 0.f;
                C[(((size_t)(bI * N + n)) << 9) + l]           = acc[mi][ni][0] + b0;
                C[(((size_t)(bI * N + n + 1)) << 9) + l]       = acc[mi][ni][1] + b1;
                C[(((size_t)(bI * N + n)) << 9) + l + 8]       = acc[mi][ni][2] + b0;
                C[(((size_t)(bI * N + n + 1)) << 9) + l + 8]   = acc[mi][ni][3] + b1;
            }
        }
    }
}

// ---------------- GroupNorm (+optional emb add) + GELU, fused; bf16 hi/lo output ----------------
__global__ void gn_gelu_kernel(const float* __restrict__ xin, const float* __restrict__ emb,
                               const float* __restrict__ scale, const float* __restrict__ bias,
                               float* __restrict__ x1_out,
                               unsigned short* __restrict__ hhi, unsigned short* __restrict__ hlo) {
    int b = blockIdx.x >> 5;
    int g = blockIdx.x & 31;
    size_t base = ((size_t)b * CC + g * CPG) * LL;
    __shared__ float vals[CPG * LL];
    __shared__ float red[256];
    int tid = threadIdx.x;
    float s = 0.f, s2 = 0.f;
#pragma unroll
    for (int i = 0; i < 16; i++) {
        int j = tid + i * 256;
        float v = xin[base + j];
        if (emb) v += emb[base + j];
        vals[j] = v;
        s += v;
        s2 = fmaf(v, v, s2);
    }
    red[tid] = s; __syncthreads();
    for (int o = 128; o > 0; o >>= 1) { if (tid < o) red[tid] += red[tid + o]; __syncthreads(); }
    float mean = red[0] * (1.f / 4096.f);
    __syncthreads();
    red[tid] = s2; __syncthreads();
    for (int o = 128; o > 0; o >>= 1) { if (tid < o) red[tid] += red[tid + o]; __syncthreads(); }
    float var = red[0] * (1.f / 4096.f) - mean * mean;
    float rsig = rsqrtf(var + 1e-5f);
#pragma unroll
    for (int i = 0; i < 16; i++) {
        int j = tid + i * 256;
        int c = g * CPG + (j >> 9);
        float v = vals[j];
        if (x1_out) x1_out[base + j] = v;
        float nn = (v - mean) * rsig * scale[c] + bias[c];
        float hv = gelu_exact(nn);
        unsigned short hu, lu;
        split_bf16(hv, hu, lu);
        hhi[base + j] = hu;
        hlo[base + j] = lu;
    }
}

// ---------------- qkv split ----------------
__global__ void qkv_split_kernel(const float* __restrict__ t, float* __restrict__ Q,
                                 float* __restrict__ K, float* __restrict__ V) {
    int idx = blockIdx.x * 256 + threadIdx.x;
    int d = idx & 31;
    int l = (idx >> 5) & 511;
    int h = (idx >> 14) & 7;
    int b = idx >> 17;
    size_t base = ((size_t)(b * LL + l)) * 768 + (size_t)(d * NH + h) * 3;
    int o = ((b * NH + h) * LL + l) * DH + d;
    Q[o] = t[base];
    K[o] = t[base + 1];
    V[o] = t[base + 2];
}

// ---------------- fused flash attention: scores + online softmax + AV ----------------
// grid (8 q-tiles, 64 bh), 256 threads. Writes oc[b,l, d*H + h].
__global__ void fused_attn_kernel(const float* __restrict__ Q, const float* __restrict__ K,
                                  const float* __restrict__ V, float* __restrict__ OCb) {
    int bh = blockIdx.y;
    int q0 = blockIdx.x * 64;
    int b = bh >> 3, h = bh & 7;
    __shared__ float Qs[64][33];
    __shared__ float Ks[64][33];
    __shared__ float Vs[64][33];
    __shared__ float Ps[64][65];
    __shared__ float rowm[64], rowl[64], rowscale[64];
    int tid = threadIdx.x;
    int d = tid & 31, qg = tid >> 5;
    int tx = tid & 15, ty = tid >> 4;
    const float sc = 0.17677669529663687f;   // 1/sqrt(32)

#pragma unroll
    for (int i = 0; i < 8; i++) {
        int idx = tid + i * 256;
        int r = idx >> 5, dd = idx & 31;
        Qs[r][dd] = Q[((size_t)(bh << 9) + q0 + r) * 32 + dd];
    }
    if (tid < 64) { rowm[tid] = -3.4e38f; rowl[tid] = 0.f; }
    float acc[8];
#pragma unroll
    for (int j = 0; j < 8; j++) acc[j] = 0.f;

    for (int k0 = 0; k0 < 512; k0 += 64) {
        __syncthreads();   // previous iteration's Ps/Vs fully consumed
#pragma unroll
        for (int i = 0; i < 8; i++) {
            int idx = tid + i * 256;
            int r = idx >> 5, dd = idx & 31;
            size_t gsrc = ((size_t)(bh << 9) + k0 + r) * 32 + dd;
            Ks[r][dd] = K[gsrc];
            Vs[r][dd] = V[gsrc];
        }
        __syncthreads();
        // ---- scores: 16x16 threads, each 4x4 ----
        {
            float sacc[4][4] = {};
#pragma unroll
            for (int kk = 0; kk < 32; kk++) {
                float a[4], bq[4];
#pragma unroll
                for (int i = 0; i < 4; i++) a[i] = Qs[ty * 4 + i][kk];
#pragma unroll
                for (int j = 0; j < 4; j++) bq[j] = Ks[tx * 4 + j][kk];
#pragma unroll
                for (int i = 0; i < 4; i++)
#pragma unroll
                    for (int j = 0; j < 4; j++) sacc[i][j] = fmaf(a[i], bq[j], sacc[i][j]);
            }
#pragma unroll
            for (int i = 0; i < 4; i++)
#pragma unroll
                for (int j = 0; j < 4; j++)
                    Ps[ty * 4 + i][tx * 4 + j] = sacc[i][j] * sc;
        }
        __syncthreads();
        // ---- row stats + exp write: 4 threads per row ----
        {
            int r = tid >> 2, sub = tid & 3;
            float mloc = -3.4e38f;
#pragma unroll
            for (int c = 0; c < 16; c++) mloc = fmaxf(mloc, Ps[r][sub * 16 + c]);
            mloc = fmaxf(mloc, __shfl_xor_sync(0xffffffff, mloc, 1));
            mloc = fmaxf(mloc, __shfl_xor_sync(0xffffffff, mloc, 2));
            float mold = rowm[r];
            float mnew = fmaxf(mold, mloc);
            float ssum = 0.f;
#pragma unroll
            for (int c = 0; c < 16; c++) {
                float e = expf(Ps[r][sub * 16 + c] - mnew);
                Ps[r][sub * 16 + c] = e;
                ssum += e;
            }
            ssum += __shfl_xor_sync(0xffffffff, ssum, 1);
            ssum += __shfl_xor_sync(0xffffffff, ssum, 2);
            if (sub == 0) {
                float scl = expf(mold - mnew);
                rowscale[r] = scl;
                rowl[r] = rowl[r] * scl + ssum;
                rowm[r] = mnew;
            }
        }
        __syncthreads();
        // ---- AV accumulate ----
#pragma unroll
        for (int j = 0; j < 8; j++) acc[j] *= rowscale[qg + j * 8];
#pragma unroll
        for (int kk = 0; kk < 64; kk++) {
            float vv = Vs[kk][d];
#pragma unroll
            for (int j = 0; j < 8; j++) acc[j] = fmaf(Ps[qg + j * 8][kk], vv, acc[j]);
        }
    }
#pragma unroll
    for (int j = 0; j < 8; j++) {
        int q = q0 + qg + j * 8;
        OCb[((size_t)(b << 9) + q) * 256 + d * NH + h] = acc[j] / rowl[qg + j * 8];
    }
}

// ---------------- MoE gating ----------------
__global__ void gating_kernel(const float* __restrict__ logits, float* __restrict__ raw,
                              float* __restrict__ g1, int* __restrict__ i1,
                              float* __restrict__ g2, int* __restrict__ i2) {
    int row = blockIdx.x;
    int tid = threadIdx.x;
    const float* p = logits + (size_t)row * EE;
    float lv[4];
#pragma unroll
    for (int j = 0; j < 4; j++) lv[j] = p[tid * 4 + j];
    __shared__ float sv[256];
    __shared__ int si[256];
    float bv = lv[0]; int bi = tid * 4;
#pragma unroll
    for (int j = 1; j < 4; j++) if (lv[j] > bv) { bv = lv[j]; bi = tid * 4 + j; }
    sv[tid] = bv; si[tid] = bi; __syncthreads();
    for (int o = 128; o > 0; o >>= 1) {
        if (tid < o) {
            if (sv[tid + o] > sv[tid] || (sv[tid + o] == sv[tid] && si[tid + o] < si[tid])) {
                sv[tid] = sv[tid + o]; si[tid] = si[tid + o];
            }
        }
        __syncthreads();
    }
    float maxv = sv[0]; int maxi = si[0];
    __syncthreads();
    float s = 0.f;
#pragma unroll
    for (int j = 0; j < 4; j++) s += expf(lv[j] - maxv);
    sv[tid] = s; __syncthreads();
    for (int o = 128; o > 0; o >>= 1) { if (tid < o) sv[tid] += sv[tid + o]; __syncthreads(); }
    float inv = 1.f / sv[0];
#pragma unroll
    for (int j = 0; j < 4; j++)
        raw[(size_t)row * EE + tid * 4 + j] = expf(lv[j] - maxv) * inv;
    __syncthreads();
    bv = -3.4e38f; bi = 0;
#pragma unroll
    for (int j = 0; j < 4; j++) {
        int e = tid * 4 + j;
        if (e != maxi && lv[j] > bv) { bv = lv[j]; bi = e; }
    }
    sv[tid] = bv; si[tid] = bi; __syncthreads();
    for (int o = 128; o > 0; o >>= 1) {
        if (tid < o) {
            if (sv[tid + o] > sv[tid] || (sv[tid + o] == sv[tid] && si[tid + o] < si[tid])) {
                sv[tid] = sv[tid + o]; si[tid] = si[tid + o];
            }
        }
        __syncthreads();
    }
    if (tid == 0) {
        float gate1v = inv;
        float gate2v = expf(sv[0] - maxv) * inv;
        float denom = gate1v + gate2v + 1e-9f;
        g1[row] = gate1v / denom;
        i1[row] = maxi;
        g2[row] = gate2v / denom;
        i2[row] = si[0];
    }
}

// ---------------- per-(b,e) sum of raw over tokens ----------------
__global__ void rawsum_kernel(const float* __restrict__ raw, float* __restrict__ rawsum) {
    int b = blockIdx.x >> 2;
    int chunk = blockIdx.x & 3;
    int e = chunk * 256 + threadIdx.x;
    const float* p = raw + (size_t)b * NTOK * EE + e;
    float s = 0.f;
    for (int n = 0; n < NTOK; n++) s += p[(size_t)n * EE];
    rawsum[b * EE + e] = s;
}

// ---------------- routing with capacity ----------------
__global__ void routing_kernel(const int* __restrict__ idx1, const float* __restrict__ gate1,
                               const int* __restrict__ idx2, const float* __restrict__ gate2,
                               int* __restrict__ slot_tok, float* __restrict__ slot_gate,
                               float* __restrict__ cnt1_out) {
    int b = blockIdx.x;
    int tid = threadIdx.x;
    __shared__ int cnt[EE];
    __shared__ int mcnt[EE];
    for (int e = tid; e < EE; e += 256) cnt[e] = 0;
    for (int i = tid; i < EE * CAPP; i += 256) {
        slot_tok[b * EE * CAPP + i] = -1;
        slot_gate[b * EE * CAPP + i] = 0.f;
    }
    __syncthreads();
    if (tid == 0) {
        for (int n = 0; n < NTOK; n++) {
            int e = idx1[b * NTOK + n];
            int pcur = cnt[e]++;
            if (pcur < CAPP) {
                slot_tok[(b * EE + e) * CAPP + pcur] = n;
                slot_gate[(b * EE + e) * CAPP + pcur] = gate1[b * NTOK + n];
            }
        }
    }
    __syncthreads();
    for (int e = tid; e < EE; e += 256) {
        cnt1_out[b * EE + e] = (float)cnt[e];
        mcnt[e] = cnt[e] < CAPP ? cnt[e] : CAPP;
        cnt[e] = 0;
    }
    __syncthreads();
    if (tid == 0) {
        for (int n = 0; n < NTOK; n++) {
            int e = idx2[b * NTOK + n];
            int pcur = mcnt[e] + cnt[e];
            cnt[e]++;
            if (pcur < CAPP) {
                slot_tok[(b * EE + e) * CAPP + pcur] = n;
                slot_gate[(b * EE + e) * CAPP + pcur] = gate2[b * NTOK + n];
            }
        }
    }
}

// ---------------- expert FFN (float4 weight staging) ----------------
__global__ void expert_kernel(const float* __restrict__ xm, const float* __restrict__ w1,
                              const float* __restrict__ w2,
                              const int* __restrict__ slot_tok, const float* __restrict__ slot_gate,
                              float* __restrict__ out) {
    int e = blockIdx.x;
    int tid = threadIdx.x;
    extern __shared__ float sw[];          // 64 KB
    __shared__ float hsh[32][33];
    __shared__ int stok[32];
    __shared__ float sgate[32];
    __shared__ int s_any;
    if (tid < 32) {
        int b = tid >> 2, c = tid & 3;
        stok[tid]  = slot_tok [(b * EE + e) * CAPP + c];
        sgate[tid] = slot_gate[(b * EE + e) * CAPP + c];
    }
    if (tid == 0) s_any = 0;
    __syncthreads();
    if (tid == 0) {
        int a = 0;
        for (int i = 0; i < 32; i++) a |= (stok[i] >= 0);
        s_any = a;
    }
    __syncthreads();
    if (!s_any) return;
    {
        const float4* w1v = (const float4*)(w1 + (size_t)e * DTOK * HIDD);
        float4* swv = (float4*)sw;
#pragma unroll
        for (int i = 0; i < 16; i++) swv[tid + i * 256] = w1v[tid + i * 256];
    }
    __syncthreads();
    int hid = tid & 31;
#pragma unroll
    for (int pass = 0; pass < 4; pass++) {
        int sidx = pass * 8 + (tid >> 5);
        int tok = stok[sidx];
        float acc = 0.f;
        if (tok >= 0) {
            const float* xr = xm + ((size_t)((sidx >> 2) * NTOK + tok)) * DTOK;
            for (int dd = 0; dd < DTOK; dd++) acc = fmaf(xr[dd], sw[dd * HIDD + hid], acc);
        }
        hsh[sidx][hid] = gelu_exact(acc);
    }
    __syncthreads();
    {
        const float4* w2v = (const float4*)(w2 + (size_t)e * HIDD * DTOK);
        float4* swv = (float4*)sw;
#pragma unroll
        for (int i = 0; i < 16; i++) swv[tid + i * 256] = w2v[tid + i * 256];
    }
    __syncthreads();
#pragma unroll
    for (int i = 0; i < 64; i++) {
        int idx = tid + i * 256;
        int sidx = idx >> 9;
        int dd = idx & 511;
        int tok = stok[sidx];
        float g = sgate[sidx];
        if (tok >= 0 && g != 0.f) {
            float acc = 0.f;
#pragma unroll
            for (int h2 = 0; h2 < HIDD; h2++) acc = fmaf(hsh[sidx][h2], sw[h2 * DTOK + dd], acc);
            atomicAdd(&out[((size_t)((sidx >> 2) * NTOK + tok)) * DTOK + dd], g * acc);
        }
    }
}

// ---------------- aux loss ----------------
__global__ void loss_kernel(const float* __restrict__ rawsum, const float* __restrict__ cnt1,
                            float* __restrict__ out_scalar) {
    __shared__ float red[256];
    int tid = threadIdx.x;
    float s = 0.f;
    for (int i = tid; i < BB * EE; i += 256) s += rawsum[i] * cnt1[i];
    red[tid] = s; __syncthreads();
    for (int o = 128; o > 0; o >>= 1) { if (tid < o) red[tid] += red[tid + o]; __syncthreads(); }
    if (tid == 0) out_scalar[0] = red[0] * 1.953125e-05f;
}

// ---------------- maxpool k=3 s=2 pad=1 ----------------
__global__ void maxpool_kernel(const float* __restrict__ yf, float* __restrict__ out) {
    int idx = blockIdx.x * 256 + threadIdx.x;
    int j = idx & 255;
    int o = (idx >> 8) & 511;
    int b = idx >> 17;
    const float* row = yf + ((size_t)(b * 512 + o)) * 512;
    int l = 2 * j;
    float m = row[l];
    if (l > 0) m = fmaxf(m, row[l - 1]);
    m = fmaxf(m, row[l + 1]);
    out[idx] = m;
}

// ---------------- host orchestration ----------------
extern "C" void kernel_launch(void* const* d_in, const int* in_sizes, int n_in,
                              void* d_out, int out_size) {
    const float* x        = (const float*)d_in[0];
    const float* emb      = (const float*)d_in[1];
    const float* rb1_g1s  = (const float*)d_in[2];
    const float* rb1_g1b  = (const float*)d_in[3];
    const float* rb1_c1w  = (const float*)d_in[4];
    const float* rb1_c1b  = (const float*)d_in[5];
    const float* rb1_g2s  = (const float*)d_in[6];
    const float* rb1_g2b  = (const float*)d_in[7];
    const float* rb1_c2w  = (const float*)d_in[8];
    const float* rb1_c2b  = (const float*)d_in[9];
    const float* rb2_g1s  = (const float*)d_in[10];
    const float* rb2_g1b  = (const float*)d_in[11];
    const float* rb2_c1w  = (const float*)d_in[12];
    const float* rb2_c1b  = (const float*)d_in[13];
    const float* rb2_g2s  = (const float*)d_in[14];
    const float* rb2_g2b  = (const float*)d_in[15];
    const float* rb2_c2w  = (const float*)d_in[16];
    const float* rb2_c2b  = (const float*)d_in[17];
    const float* attn_w1  = (const float*)d_in[18];
    const float* attn_b1  = (const float*)d_in[19];
    const float* attn_w2  = (const float*)d_in[20];
    const float* attn_b2  = (const float*)d_in[21];
    const float* moe_wg   = (const float*)d_in[22];
    const float* moe_w1   = (const float*)d_in[23];
    const float* moe_w2   = (const float*)d_in[24];
    const float* out_w    = (const float*)d_in[25];
    const float* out_b    = (const float*)d_in[26];
    float* out = (float*)d_out;

    float *px1, *pr, *pxa, *pt, *pq, *pk, *pv, *poc, *pxb, *pxm;
    float *plog, *praw, *pg1, *pg2, *prs, *pc1, *psg, *pmo, *pyf;
    int *pi1, *pi2, *pst;
    unsigned short *pwhi, *pwlo, *phhi, *phlo;
    cudaGetSymbolAddress((void**)&px1, g_x1);
    cudaGetSymbolAddress((void**)&pr,  g_r);
    cudaGetSymbolAddress((void**)&pxa, g_xa);
    cudaGetSymbolAddress((void**)&pt,  g_t);
    cudaGetSymbolAddress((void**)&pq,  g_q);
    cudaGetSymbolAddress((void**)&pk,  g_k);
    cudaGetSymbolAddress((void**)&pv,  g_v);
    cudaGetSymbolAddress((void**)&poc, g_oc);
    cudaGetSymbolAddress((void**)&pxb, g_xb);
    cudaGetSymbolAddress((void**)&pxm, g_xm);
    cudaGetSymbolAddress((void**)&plog, g_logits);
    cudaGetSymbolAddress((void**)&praw, g_raw);
    cudaGetSymbolAddress((void**)&pg1, g_gate1);
    cudaGetSymbolAddress((void**)&pg2, g_gate2);
    cudaGetSymbolAddress((void**)&pi1, g_i1);
    cudaGetSymbolAddress((void**)&pi2, g_i2);
    cudaGetSymbolAddress((void**)&prs, g_rawsum);
    cudaGetSymbolAddress((void**)&pc1, g_cnt1);
    cudaGetSymbolAddress((void**)&pst, g_slot_tok);
    cudaGetSymbolAddress((void**)&psg, g_slot_gate);
    cudaGetSymbolAddress((void**)&pmo, g_moeout);
    cudaGetSymbolAddress((void**)&pyf, g_yfull);
    cudaGetSymbolAddress((void**)&pwhi, g_whi);
    cudaGetSymbolAddress((void**)&pwlo, g_wlo);
    cudaGetSymbolAddress((void**)&phhi, g_hhi);
    cudaGetSymbolAddress((void**)&phlo, g_hlo);

    cudaFuncSetAttribute(expert_kernel, cudaFuncAttributeMaxDynamicSharedMemorySize, 65536);
    cudaFuncSetAttribute(conv_mma_kernel, cudaFuncAttributeMaxDynamicSharedMemorySize, MMA_SMEM);
    cudaFuncSetAttribute(gemm_mma<0,3>, cudaFuncAttributeMaxDynamicSharedMemorySize, MMA_SMEM);
    cudaFuncSetAttribute(gemm_mma<2,3>, cudaFuncAttributeMaxDynamicSharedMemorySize, MMA_SMEM);
    cudaFuncSetAttribute(gemm_mma<0,4>, cudaFuncAttributeMaxDynamicSharedMemorySize, MMA_SMEM);

    const int WSZc = WSZ;
    // ---- pre-convert weights ----
    cvt_hilo_kernel<<<768, 256>>>(rb1_c1w, pwhi,          pwlo,          WSZc);
    cvt_hilo_kernel<<<768, 256>>>(rb1_c2w, pwhi + WSZc,   pwlo + WSZc,   WSZc);
    cvt_hilo_kernel<<<768, 256>>>(rb2_c1w, pwhi + 2*WSZc, pwlo + 2*WSZc, WSZc);
    cvt_hilo_kernel<<<768, 256>>>(rb2_c2w, pwhi + 3*WSZc, pwlo + 3*WSZc, WSZc);
    cvt_hilo_kernel<<<1536, 256>>>(out_w,  pwhi + 4*WSZc, pwlo + 4*WSZc, 2*WSZc);
    cvtT_w_kernel<<<dim3(8, 24), dim3(32, 8)>>>(attn_w1, pwhi + OFF_WQKVT, pwlo + OFF_WQKVT, 256, 768);
    cvtT_w_kernel<<<dim3(8, 8),  dim3(32, 8)>>>(attn_w2, pwhi + OFF_W2T,   pwlo + OFF_W2T,   256, 256);
    cvtT_w_kernel<<<dim3(16, 32), dim3(32, 8)>>>(moe_wg, pwhi + OFF_WGT,   pwlo + OFF_WGT,   512, 1024);

    // ---- res block 1 ----
    gn_gelu_kernel<<<BB * NG, 256>>>(x, emb, rb1_g1s, rb1_g1b, px1, phhi, phlo);
    conv_mma_kernel<<<dim3(32, 4), 256, MMA_SMEM>>>(pwhi, pwlo, phhi, phlo, rb1_c1b, nullptr, pr, 256);
    gn_gelu_kernel<<<BB * NG, 256>>>(pr, nullptr, rb1_g2s, rb1_g2b, nullptr, phhi, phlo);
    conv_mma_kernel<<<dim3(32, 4), 256, MMA_SMEM>>>(pwhi + WSZc, pwlo + WSZc, phhi, phlo, rb1_c2b, px1, pxa, 256);

    // ---- attention ----
    cvtT_x_kernel<<<dim3(16, 8, 8), dim3(32, 8)>>>(pxa, phhi, phlo);
    gemm_mma<0,3><<<dim3(6, 64), 256, MMA_SMEM>>>(phhi, phlo, pwhi + OFF_WQKVT, pwlo + OFF_WQKVT,
                                                  attn_b1, pt, 4096, 768, 256);
    qkv_split_kernel<<<4096, 256>>>(pt, pq, pk, pv);
    fused_attn_kernel<<<dim3(8, 64), 256>>>(pq, pk, pv, poc);
    cvt_hilo_kernel<<<4096, 256>>>(poc, phhi, phlo, BB * LL * CC);
    gemm_mma<2,3><<<dim3(2, 64), 256, MMA_SMEM>>>(phhi, phlo, pwhi + OFF_W2T, pwlo + OFF_W2T,
                                                  attn_b2, pxb, 4096, 256, 256);

    // ---- res block 2 ----
    gn_gelu_kernel<<<BB * NG, 256>>>(pxb, emb, rb2_g1s, rb2_g1b, px1, phhi, phlo);
    conv_mma_kernel<<<dim3(32, 4), 256, MMA_SMEM>>>(pwhi + 2*WSZc, pwlo + 2*WSZc, phhi, phlo, rb2_c1b, nullptr, pr, 256);
    gn_gelu_kernel<<<BB * NG, 256>>>(pr, nullptr, rb2_g2s, rb2_g2b, nullptr, phhi, phlo);
    conv_mma_kernel<<<dim3(32, 4), 256, MMA_SMEM>>>(pwhi + 3*WSZc, pwlo + 3*WSZc, phhi, phlo, rb2_c2b, px1, pxm, 256);

    // ---- MoE ----
    cvt_hilo_kernel<<<4096, 256>>>(pxm, phhi, phlo, BB * CC * LL);
    gemm_mma<0,4><<<dim3(8, 32), 256, MMA_SMEM>>>(phhi, phlo, pwhi + OFF_WGT, pwlo + OFF_WGT,
                                                  nullptr, plog, 2048, 1024, 512);
    gating_kernel<<<2048, 256>>>(plog, praw, pg1, pi1, pg2, pi2);
    rawsum_kernel<<<32, 256>>>(praw, prs);
    routing_kernel<<<BB, 256>>>(pi1, pg1, pi2, pg2, pst, psg, pc1);
    cudaMemsetAsync(pmo, 0, sizeof(float) * BB * CC * LL);
    expert_kernel<<<EE, 256, 65536>>>(pxm, moe_w1, moe_w2, pst, psg, pmo);
    loss_kernel<<<1, 256>>>(prs, pc1, out + 2097152);

    // ---- output conv + maxpool ----
    cvt_hilo_kernel<<<4096, 256>>>(pmo, phhi, phlo, BB * CC * LL);
    conv_mma_kernel<<<dim3(32, 8), 256, MMA_SMEM>>>(pwhi + 4*WSZc, pwlo + 4*WSZc, phhi, phlo, out_b, nullptr, pyf, 512);
    maxpool_kernel<<<4096, 256>>>(pyf, out);

    // second output: moe result x (B,C,L)
    cudaMemcpyAsync(out + 1048576, pmo, sizeof(float) * BB * CC * LL, cudaMemcpyDeviceToDevice);
}